// round 8
// baseline (speedup 1.0000x reference)
#include <cuda_runtime.h>
#include <cuda_bf16.h>
#include <math.h>
#include <cstdint>

#define NN 4096
#define DD 128
#define HH 4
#define NMID 9
#define PSTR 40  // bf16 elems per smem row (80B, ldmatrix conflict-free)

typedef unsigned long long u64;

// ===========================================================================
// PTX helpers (sm_80-class: compiles for plain sm_103)
// ===========================================================================
__device__ __forceinline__ uint32_t smem_u32(const void* p) {
    uint32_t a;
    asm("{ .reg .u64 t; cvta.to.shared.u64 t, %1; cvt.u32.u64 %0, t; }" : "=r"(a) : "l"(p));
    return a;
}
__device__ __forceinline__ void ldsm_x4(unsigned* r, uint32_t addr) {
    asm volatile("ldmatrix.sync.aligned.m8n8.x4.shared.b16 {%0,%1,%2,%3}, [%4];"
                 : "=r"(r[0]), "=r"(r[1]), "=r"(r[2]), "=r"(r[3]) : "r"(addr));
}
__device__ __forceinline__ void mma_bf16(float* d, const unsigned* a, const unsigned* b) {
    asm volatile(
        "mma.sync.aligned.m16n8k16.row.col.f32.bf16.bf16.f32 "
        "{%0,%1,%2,%3}, {%4,%5,%6,%7}, {%8,%9}, {%0,%1,%2,%3};"
        : "+f"(d[0]), "+f"(d[1]), "+f"(d[2]), "+f"(d[3])
        : "r"(a[0]), "r"(a[1]), "r"(a[2]), "r"(a[3]), "r"(b[0]), "r"(b[1]));
}
__device__ __forceinline__ void cp16(uint32_t dst, const void* src) {
    asm volatile("cp.async.ca.shared.global [%0], [%1], 16;" :: "r"(dst), "l"(src) : "memory");
}
#define CP_COMMIT() asm volatile("cp.async.commit_group;" ::: "memory")
#define CP_WAIT0()  asm volatile("cp.async.wait_group 0;" ::: "memory")

// ===========================================================================
// Scratch (device globals)
// ===========================================================================
__device__ __align__(16) float g_X0[NN * 512];
__device__ __align__(16) float g_X1[NN * 512];
__device__ __align__(16) float g_Wh[HH * NN * DD];
__device__ __align__(16) __nv_bfloat16 g_WhT_hi[HH * DD * NN];  // [h][n=128][k=4096]
__device__ __align__(16) __nv_bfloat16 g_WhT_lo[HH * DD * NN];
__device__ __align__(16) __nv_bfloat16 g_Xhi[NN * 512];
__device__ __align__(16) __nv_bfloat16 g_Xlo[NN * 512];
__device__ __align__(16) __nv_bfloat16 g_Wt_hi[HH * DD * 512];  // [h][n=128][k<=512]
__device__ __align__(16) __nv_bfloat16 g_Wt_lo[HH * DD * 512];
__device__ float g_f1[HH * NN];
__device__ float g_f2[HH * NN];
__device__ float g_m[HH * NN];
__device__ float g_si[HH * NN];
__device__ __align__(16) float g_rowA[HH * NN];
__device__ __align__(16) float g_rowC[HH * NN];
__device__ __align__(16) float g_colB[HH * NN];
__device__ __align__(16) float g_colD[HH * NN];
__device__ unsigned g_mask[NN * 128];

// ===========================================================================
// adj > 0 -> bitmask
// ===========================================================================
__global__ void build_mask_kernel(const float* __restrict__ adj,
                                  unsigned* __restrict__ mask) {
    int i = blockIdx.x;
    int t = threadIdx.x;
    int lane = t & 31;
    const float* row = adj + (size_t)i * NN;
    for (int word = t >> 5; word < 128; word += 8) {
        float v = row[word * 32 + lane];
        unsigned b = __ballot_sync(0xffffffffu, v > 0.f);
        if (lane == 0) mask[i * 128 + word] = b;
    }
}

__global__ void hrc_kernel(const int* __restrict__ head, const int* __restrict__ rel,
                           const float* __restrict__ ee, const float* __restrict__ re,
                           float* __restrict__ out) {
    int i = blockIdx.x;
    int d = threadIdx.x;
    out[(size_t)i * 128 + d] =
        ee[(size_t)head[i] * 128 + d] + re[(size_t)rel[i] * 128 + d];
}

// ===========================================================================
// fp32 -> bf16 hi/lo split (flat)
// ===========================================================================
__global__ void split_kernel(const float* __restrict__ src,
                             __nv_bfloat16* __restrict__ hi,
                             __nv_bfloat16* __restrict__ lo, int n) {
    int i = blockIdx.x * 256 + threadIdx.x;
    if (i < n) {
        float v = src[i];
        __nv_bfloat16 h = __float2bfloat16(v);
        hi[i] = h;
        lo[i] = __float2bfloat16(v - __bfloat162float(h));
    }
}

// ===========================================================================
// transpose + split: src fp32 [h][kdim][128] -> hi/lo bf16 [h][128][kdim]
// grid (kdim/32, 4, H)
// ===========================================================================
__global__ void wt_split_kernel(const float* __restrict__ src,
                                __nv_bfloat16* __restrict__ dhi,
                                __nv_bfloat16* __restrict__ dlo, int kdim) {
    int h = blockIdx.z;
    int kbase = blockIdx.x * 32;
    int nbase = blockIdx.y * 32;
    __shared__ float ts[32][33];
    const float* sp = src + (size_t)h * kdim * 128;
    int t = threadIdx.x;
#pragma unroll
    for (int l = 0; l < 4; l++) {
        int e = t + l * 256;
        int r = e >> 5, c = e & 31;
        ts[r][c] = sp[(size_t)(kbase + r) * 128 + nbase + c];
    }
    __syncthreads();
#pragma unroll
    for (int l = 0; l < 4; l++) {
        int e = t + l * 256;
        int r = e >> 5, c = e & 31;  // r = n-local, c = k-local
        float v = ts[c][r];
        __nv_bfloat16 hi = __float2bfloat16(v);
        __nv_bfloat16 lo = __float2bfloat16(v - __bfloat162float(hi));
        size_t o = (size_t)(h * 128 + nbase + r) * kdim + kbase + c;
        dhi[o] = hi;
        dlo[o] = lo;
    }
}

// ===========================================================================
// Tensorized Wh = X @ W : A = Xhi/lo [m][k], B = Wt hi/lo [h][n=128][k=Fin]
// CTA: 64m x 128n, grid (64, H).
// ===========================================================================
__global__ void __launch_bounds__(256)
gemm_mma_kernel(const __nv_bfloat16* __restrict__ Xhi, const __nv_bfloat16* __restrict__ Xlo,
                const __nv_bfloat16* __restrict__ WtHi, const __nv_bfloat16* __restrict__ WtLo,
                float* __restrict__ Wh, int Fin) {
    __shared__ __align__(16) __nv_bfloat16 Ahi[64][PSTR];
    __shared__ __align__(16) __nv_bfloat16 Alo[64][PSTR];
    __shared__ __align__(16) __nv_bfloat16 Bhi[128][PSTR];
    __shared__ __align__(16) __nv_bfloat16 Blo[128][PSTR];

    int h = blockIdx.y;
    int row0 = blockIdx.x * 64;
    int t = threadIdx.x, wid = t >> 5, lane = t & 31;
    int wr = wid & 3, wc = wid >> 2;
    const __nv_bfloat16* Wth = WtHi + (size_t)h * 128 * Fin;
    const __nv_bfloat16* Wtl = WtLo + (size_t)h * 128 * Fin;
    float* outp = Wh + (size_t)h * NN * 128;

    uint32_t sAhi = smem_u32(Ahi), sAlo = smem_u32(Alo);
    uint32_t sBhi = smem_u32(Bhi), sBlo = smem_u32(Blo);
    float d[8][4] = {};

    uint32_t a_off = (uint32_t)(wr * 16 + ((lane >> 3) & 1) * 8 + (lane & 7)) * (PSTR * 2)
                   + (uint32_t)((lane >> 4) * 8) * 2;
    uint32_t b_roff = (uint32_t)(wc * 64 + (lane >> 4) * 8 + (lane & 7)) * (PSTR * 2);
    uint32_t b_koff = (uint32_t)(((lane >> 3) & 1) * 8) * 2;

    for (int k0 = 0; k0 < Fin; k0 += 32) {
        __syncthreads();
        {
            int m = t >> 2, q = t & 3;
            size_t go = (size_t)(row0 + m) * Fin + k0 + q * 8;
            *(uint4*)&Ahi[m][q * 8] = *(const uint4*)(Xhi + go);
            *(uint4*)&Alo[m][q * 8] = *(const uint4*)(Xlo + go);
        }
#pragma unroll
        for (int l = 0; l < 2; l++) {
            int idx = t + l * 256;
            int n = idx >> 2, q = idx & 3;
            size_t go = (size_t)n * Fin + k0 + q * 8;
            *(uint4*)&Bhi[n][q * 8] = *(const uint4*)(Wth + go);
            *(uint4*)&Blo[n][q * 8] = *(const uint4*)(Wtl + go);
        }
        __syncthreads();
#pragma unroll
        for (int s = 0; s < 2; s++) {
            unsigned ah[4], al[4];
            ldsm_x4(ah, sAhi + a_off + s * 32);
            ldsm_x4(al, sAlo + a_off + s * 32);
#pragma unroll
            for (int pp = 0; pp < 4; pp++) {
                unsigned bh[4], bl[4];
                uint32_t boff = b_roff + (uint32_t)(pp * 16) * (PSTR * 2) + b_koff + s * 32;
                ldsm_x4(bh, sBhi + boff);
                ldsm_x4(bl, sBlo + boff);
                mma_bf16(d[2 * pp],     ah, bh);
                mma_bf16(d[2 * pp + 1], ah, bh + 2);
                mma_bf16(d[2 * pp],     ah, bl);
                mma_bf16(d[2 * pp + 1], ah, bl + 2);
                mma_bf16(d[2 * pp],     al, bh);
                mma_bf16(d[2 * pp + 1], al, bh + 2);
            }
        }
    }
    int r0 = row0 + wr * 16 + (lane >> 2);
    int cbase = wc * 64 + (lane & 3) * 2;
#pragma unroll
    for (int nt = 0; nt < 8; nt++) {
        int col = cbase + nt * 8;
        *(float2*)&outp[(size_t)r0 * 128 + col] = make_float2(d[nt][0], d[nt][1]);
        *(float2*)&outp[(size_t)(r0 + 8) * 128 + col] = make_float2(d[nt][2], d[nt][3]);
    }
}

// ===========================================================================
// f1/f2
// ===========================================================================
__global__ void compute_f_kernel(const float* __restrict__ Wh, const float* __restrict__ A,
                                 float* __restrict__ f1, float* __restrict__ f2) {
    int h = blockIdx.y;
    int warp = threadIdx.x >> 5, lane = threadIdx.x & 31;
    int i = blockIdx.x * 8 + warp;
    const float* row = Wh + ((size_t)h * NN + i) * 128;
    const float* a = A + h * 256;
    float s1 = 0.f, s2 = 0.f;
#pragma unroll
    for (int d = lane; d < 128; d += 32) {
        float v = row[d];
        s1 += v * a[d];
        s2 += v * a[128 + d];
    }
#pragma unroll
    for (int o = 16; o; o >>= 1) {
        s1 += __shfl_xor_sync(0xffffffffu, s1, o);
        s2 += __shfl_xor_sync(0xffffffffu, s2, o);
    }
    if (lane == 0) {
        f1[h * NN + i] = s1;
        f2[h * NN + i] = s2;
    }
}

// ===========================================================================
// softmax stats
// ===========================================================================
__global__ void stats_kernel(const float* __restrict__ f1, const float* __restrict__ f2,
                             const unsigned* __restrict__ mask,
                             float* __restrict__ mo, float* __restrict__ sio) {
    int h = blockIdx.y;
    int rowbase = blockIdx.x * 16;
    __shared__ float f2s[NN];
    __shared__ unsigned mws[16][128];
    int t = threadIdx.x;
    for (int j = t; j < NN; j += 256) f2s[j] = f2[h * NN + j];
    for (int idx = t; idx < 16 * 128; idx += 256) {
        int r = idx >> 7, w = idx & 127;
        mws[r][w] = mask[(size_t)(rowbase + r) * 128 + w];
    }
    __syncthreads();
    int warp = t >> 5, lane = t & 31;
    for (int rr = warp; rr < 16; rr += 8) {
        int i = rowbase + rr;
        float fr = f1[h * NN + i];
        float mmax = -1e30f;
        for (int w = 0; w < 128; w++) {
            unsigned msk = mws[rr][w];
            if ((msk >> lane) & 1u) {
                float e = fr + f2s[w * 32 + lane];
                e = e > 0.f ? e : 0.2f * e;
                mmax = fmaxf(mmax, e);
            }
        }
#pragma unroll
        for (int o = 16; o; o >>= 1)
            mmax = fmaxf(mmax, __shfl_xor_sync(0xffffffffu, mmax, o));
        float s = 0.f;
        for (int w = 0; w < 128; w++) {
            unsigned msk = mws[rr][w];
            if ((msk >> lane) & 1u) {
                float e = fr + f2s[w * 32 + lane];
                e = e > 0.f ? e : 0.2f * e;
                s += __expf(e - mmax);
            }
        }
#pragma unroll
        for (int o = 16; o; o >>= 1) s += __shfl_xor_sync(0xffffffffu, s, o);
        if (lane == 0) {
            mo[h * NN + i] = mmax;
            sio[h * NN + i] = 1.f / s;
        }
    }
}

// ===========================================================================
// rowA = si*exp(f1-m), rowC = si*exp(0.2f1-m), colB = exp(f2), colD = exp(0.2f2)
// ===========================================================================
__global__ void prep_vec_kernel(const float* __restrict__ f1, const float* __restrict__ f2,
                                const float* __restrict__ mm, const float* __restrict__ si,
                                float* __restrict__ rowA, float* __restrict__ rowC,
                                float* __restrict__ colB, float* __restrict__ colD) {
    int h = blockIdx.y;
    int i = blockIdx.x * 256 + threadIdx.x;
    int idx = h * NN + i;
    float m = mm[idx], s = si[idx], a = f1[idx], b = f2[idx];
    rowA[idx] = s * __expf(a - m);
    rowC[idx] = s * __expf(0.2f * a - m);
    colB[idx] = __expf(b);
    colD[idx] = __expf(0.2f * b);
}

// ===========================================================================
// Pipelined mma.sync attention. CTA 128m x 128n, grid (32, H).
// Double-buffered B (cp.async) and P tiles; 1 barrier + wait_group per chunk.
// Dynamic smem layout (bytes):
//   P[buf][hl]: (buf*2+hl)*10240        (128 rows x 80B)  total 40960
//   B[buf][hl]: 40960+(buf*2+hl)*10240  (128 rows x 80B)  total 40960
// ===========================================================================
#define ATT_SMEM 81920

__global__ void __launch_bounds__(256)
attn_mma_kernel(const __nv_bfloat16* __restrict__ WhT_hi,
                const __nv_bfloat16* __restrict__ WhT_lo,
                const float* __restrict__ rowA, const float* __restrict__ rowC,
                const float* __restrict__ colB, const float* __restrict__ colD,
                const unsigned* __restrict__ mask,
                float* __restrict__ out, int out_stride) {
    extern __shared__ __align__(16) char smem[];
    uint32_t sb = smem_u32(smem);
    const uint32_t sP = sb;
    const uint32_t sB = sb + 40960;

    int h = blockIdx.y;
    int row0 = blockIdx.x * 128;
    int hbase = h * NN;
    int t = threadIdx.x, wid = t >> 5, lane = t & 31;
    int wr = wid & 3, wc = wid >> 2;

    const __nv_bfloat16* Whh = WhT_hi + (size_t)(h * 128) * NN;
    const __nv_bfloat16* Whl = WhT_lo + (size_t)(h * 128) * NN;

    // P-gen role: thread covers row pr (0..127), two k-octets starting at (t&1)*2
    int pr = t >> 1, kq0 = (t & 1) * 2;
    float Ar = rowA[hbase + row0 + pr];
    float Cr = rowC[hbase + row0 + pr];
    const unsigned* mrow = mask + (size_t)(row0 + pr) * 128;
    const float* cBp = colB + hbase;
    const float* cDp = colD + hbase;

    // ldmatrix lane addresses (bytes); A has 2 m16 tiles per warp
    uint32_t a_off0 = (uint32_t)(wr * 32 + ((lane >> 3) & 1) * 8 + (lane & 7)) * (PSTR * 2)
                    + (uint32_t)((lane >> 4) * 8) * 2;
    uint32_t a_off1 = a_off0 + 16 * (PSTR * 2);
    uint32_t b_roff = (uint32_t)(wc * 64 + (lane >> 4) * 8 + (lane & 7)) * (PSTR * 2);
    uint32_t b_koff = (uint32_t)(((lane >> 3) & 1) * 8) * 2;

    float d[2][8][4] = {};

    auto stage = [&](int c, int buf) {
#pragma unroll
        for (int l = 0; l < 2; l++) {
            int idx = t + l * 256;
            int n = idx >> 2, q = idx & 3;
            size_t go = (size_t)n * NN + c * 32 + q * 8;
            cp16(sB + (uint32_t)(buf * 2 + 0) * 10240 + n * 80 + q * 16, Whh + go);
            cp16(sB + (uint32_t)(buf * 2 + 1) * 10240 + n * 80 + q * 16, Whl + go);
        }
        CP_COMMIT();
    };
    auto pgen = [&](int c, int buf) {
        unsigned w32 = mrow[c];
#pragma unroll
        for (int j2 = 0; j2 < 2; j2++) {
            int kq = kq0 + j2;
            int kb = c * 32 + kq * 8;
            unsigned w8 = w32 >> (kq * 8);
            float4 b0 = *(const float4*)(cBp + kb);
            float4 b1 = *(const float4*)(cBp + kb + 4);
            float4 d0 = *(const float4*)(cDp + kb);
            float4 d1 = *(const float4*)(cDp + kb + 4);
            float p[8];
            p[0] = (w8 & 1u)   ? fmaxf(Ar * b0.x, Cr * d0.x) : 0.f;
            p[1] = (w8 & 2u)   ? fmaxf(Ar * b0.y, Cr * d0.y) : 0.f;
            p[2] = (w8 & 4u)   ? fmaxf(Ar * b0.z, Cr * d0.z) : 0.f;
            p[3] = (w8 & 8u)   ? fmaxf(Ar * b0.w, Cr * d0.w) : 0.f;
            p[4] = (w8 & 16u)  ? fmaxf(Ar * b1.x, Cr * d1.x) : 0.f;
            p[5] = (w8 & 32u)  ? fmaxf(Ar * b1.y, Cr * d1.y) : 0.f;
            p[6] = (w8 & 64u)  ? fmaxf(Ar * b1.z, Cr * d1.z) : 0.f;
            p[7] = (w8 & 128u) ? fmaxf(Ar * b1.w, Cr * d1.w) : 0.f;
            uint4 uh, ul;
            unsigned* ph = &uh.x;
            unsigned* pl = &ul.x;
#pragma unroll
            for (int j = 0; j < 4; j++) {
                __nv_bfloat162 h2 = __floats2bfloat162_rn(p[2 * j], p[2 * j + 1]);
                float r0 = p[2 * j] - __bfloat162float(h2.x);
                float r1 = p[2 * j + 1] - __bfloat162float(h2.y);
                __nv_bfloat162 l2 = __floats2bfloat162_rn(r0, r1);
                ph[j] = *(unsigned*)&h2;
                pl[j] = *(unsigned*)&l2;
            }
            *(uint4*)(smem + (buf * 2 + 0) * 10240 + pr * 80 + kq * 16) = uh;
            *(uint4*)(smem + (buf * 2 + 1) * 10240 + pr * 80 + kq * 16) = ul;
        }
    };

    // prologue
    stage(0, 0);
    pgen(0, 0);

    for (int c = 0; c < 128; c++) {
        int buf = c & 1;
        CP_WAIT0();
        __syncthreads();     // publish B(c), P(c); all readers of buf^1 done
        if (c + 1 < 128) {
            stage(c + 1, buf ^ 1);   // overlaps with mma below
            pgen(c + 1, buf ^ 1);
        }
        uint32_t pH = sP + (uint32_t)(buf * 2 + 0) * 10240;
        uint32_t pL = sP + (uint32_t)(buf * 2 + 1) * 10240;
        uint32_t bH = sB + (uint32_t)(buf * 2 + 0) * 10240;
        uint32_t bL = sB + (uint32_t)(buf * 2 + 1) * 10240;
#pragma unroll
        for (int s = 0; s < 2; s++) {
            unsigned ah[2][4], al[2][4];
            ldsm_x4(ah[0], pH + a_off0 + s * 32);
            ldsm_x4(al[0], pL + a_off0 + s * 32);
            ldsm_x4(ah[1], pH + a_off1 + s * 32);
            ldsm_x4(al[1], pL + a_off1 + s * 32);
#pragma unroll
            for (int pp = 0; pp < 4; pp++) {
                unsigned bh[4], bl[4];
                uint32_t boff = b_roff + (uint32_t)(pp * 16) * (PSTR * 2) + b_koff + s * 32;
                ldsm_x4(bh, bH + boff);
                ldsm_x4(bl, bL + boff);
#pragma unroll
                for (int mt = 0; mt < 2; mt++) {
                    mma_bf16(d[mt][2 * pp],     ah[mt], bh);
                    mma_bf16(d[mt][2 * pp + 1], ah[mt], bh + 2);
                    mma_bf16(d[mt][2 * pp],     ah[mt], bl);
                    mma_bf16(d[mt][2 * pp + 1], ah[mt], bl + 2);
                    mma_bf16(d[mt][2 * pp],     al[mt], bh);
                    mma_bf16(d[mt][2 * pp + 1], al[mt], bh + 2);
                }
            }
        }
    }

    // epilogue: elu + write
    int cbase = h * 128 + wc * 64 + (lane & 3) * 2;
#pragma unroll
    for (int mt = 0; mt < 2; mt++) {
        int r0 = row0 + wr * 32 + mt * 16 + (lane >> 2);
#pragma unroll
        for (int nt = 0; nt < 8; nt++) {
            int col = cbase + nt * 8;
            float v0 = d[mt][nt][0], v1 = d[mt][nt][1];
            float v2 = d[mt][nt][2], v3 = d[mt][nt][3];
            v0 = v0 > 0.f ? v0 : expm1f(v0);
            v1 = v1 > 0.f ? v1 : expm1f(v1);
            v2 = v2 > 0.f ? v2 : expm1f(v2);
            v3 = v3 > 0.f ? v3 : expm1f(v3);
            *(float2*)&out[(size_t)r0 * out_stride + col] = make_float2(v0, v1);
            *(float2*)&out[(size_t)(r0 + 8) * out_stride + col] = make_float2(v2, v3);
        }
    }
}

// ===========================================================================
extern "C" void kernel_launch(void* const* d_in, const int* in_sizes, int n_in,
                              void* d_out, int out_size) {
    const int* head = (const int*)d_in[0];
    const int* rel = (const int*)d_in[1];
    const float* adj = (const float*)d_in[2];
    const float* ee = (const float*)d_in[3];
    const float* re = (const float*)d_in[4];
    const float* W0 = (const float*)d_in[5];
    const float* a0 = (const float*)d_in[6];
    const float* Wm = (const float*)d_in[7];
    const float* am = (const float*)d_in[8];
    const float* Wo = (const float*)d_in[9];
    const float* ao = (const float*)d_in[10];
    float* out = (float*)d_out;

    float *X0, *X1, *Wh, *f1, *f2, *mv, *si, *rA, *rC, *cB, *cD;
    __nv_bfloat16 *WhTh, *WhTl, *Xhi, *Xlo, *Wth, *Wtl;
    unsigned* mask;
    cudaGetSymbolAddress((void**)&X0, g_X0);
    cudaGetSymbolAddress((void**)&X1, g_X1);
    cudaGetSymbolAddress((void**)&Wh, g_Wh);
    cudaGetSymbolAddress((void**)&f1, g_f1);
    cudaGetSymbolAddress((void**)&f2, g_f2);
    cudaGetSymbolAddress((void**)&mv, g_m);
    cudaGetSymbolAddress((void**)&si, g_si);
    cudaGetSymbolAddress((void**)&rA, g_rowA);
    cudaGetSymbolAddress((void**)&rC, g_rowC);
    cudaGetSymbolAddress((void**)&cB, g_colB);
    cudaGetSymbolAddress((void**)&cD, g_colD);
    cudaGetSymbolAddress((void**)&WhTh, g_WhT_hi);
    cudaGetSymbolAddress((void**)&WhTl, g_WhT_lo);
    cudaGetSymbolAddress((void**)&Xhi, g_Xhi);
    cudaGetSymbolAddress((void**)&Xlo, g_Xlo);
    cudaGetSymbolAddress((void**)&Wth, g_Wt_hi);
    cudaGetSymbolAddress((void**)&Wtl, g_Wt_lo);
    cudaGetSymbolAddress((void**)&mask, g_mask);

    cudaFuncSetAttribute(attn_mma_kernel, cudaFuncAttributeMaxDynamicSharedMemorySize, ATT_SMEM);

    build_mask_kernel<<<NN, 256>>>(adj, mask);
    hrc_kernel<<<NN, 128>>>(head, rel, ee, re, out + (size_t)NN * 128);

    // ---- layer 0: Fin = 128, X = entity_emb ----
    split_kernel<<<(NN * 128 + 255) / 256, 256>>>(ee, Xhi, Xlo, NN * 128);
    wt_split_kernel<<<dim3(4, 4, HH), 256>>>(W0, Wth, Wtl, 128);
    gemm_mma_kernel<<<dim3(64, HH), 256>>>(Xhi, Xlo, Wth, Wtl, Wh, 128);
    compute_f_kernel<<<dim3(512, HH), 256>>>(Wh, a0, f1, f2);
    stats_kernel<<<dim3(256, HH), 256>>>(f1, f2, mask, mv, si);
    prep_vec_kernel<<<dim3(16, HH), 256>>>(f1, f2, mv, si, rA, rC, cB, cD);
    wt_split_kernel<<<dim3(128, 4, HH), 256>>>(Wh, WhTh, WhTl, NN);
    attn_mma_kernel<<<dim3(32, HH), 256, ATT_SMEM>>>(WhTh, WhTl, rA, rC, cB, cD, mask, X0, 512);

    // ---- 9 middle layers: Fin = 512 ----
    float* cur = X0;
    float* nxt = X1;
    for (int l = 0; l < NMID; l++) {
        split_kernel<<<(NN * 512 + 255) / 256, 256>>>(cur, Xhi, Xlo, NN * 512);
        wt_split_kernel<<<dim3(16, 4, HH), 256>>>(Wm + (size_t)l * HH * 512 * 128, Wth, Wtl, 512);
        gemm_mma_kernel<<<dim3(64, HH), 256>>>(Xhi, Xlo, Wth, Wtl, Wh, 512);
        compute_f_kernel<<<dim3(512, HH), 256>>>(Wh, am + (size_t)l * HH * 256, f1, f2);
        stats_kernel<<<dim3(256, HH), 256>>>(f1, f2, mask, mv, si);
        prep_vec_kernel<<<dim3(16, HH), 256>>>(f1, f2, mv, si, rA, rC, cB, cD);
        wt_split_kernel<<<dim3(128, 4, HH), 256>>>(Wh, WhTh, WhTl, NN);
        attn_mma_kernel<<<dim3(32, HH), 256, ATT_SMEM>>>(WhTh, WhTl, rA, rC, cB, cD, mask, nxt, 512);
        float* tmp = cur; cur = nxt; nxt = tmp;
    }

    // ---- output layer: 1 head, Fin = 512 ----
    split_kernel<<<(NN * 512 + 255) / 256, 256>>>(cur, Xhi, Xlo, NN * 512);
    wt_split_kernel<<<dim3(16, 4, 1), 256>>>(Wo, Wth, Wtl, 512);
    gemm_mma_kernel<<<dim3(64, 1), 256>>>(Xhi, Xlo, Wth, Wtl, Wh, 512);
    compute_f_kernel<<<dim3(512, 1), 256>>>(Wh, ao, f1, f2);
    stats_kernel<<<dim3(256, 1), 256>>>(f1, f2, mask, mv, si);
    prep_vec_kernel<<<dim3(16, 1), 256>>>(f1, f2, mv, si, rA, rC, cB, cD);
    wt_split_kernel<<<dim3(128, 4, 1), 256>>>(Wh, WhTh, WhTl, NN);
    attn_mma_kernel<<<dim3(32, 1), 256, ATT_SMEM>>>(WhTh, WhTl, rA, rC, cB, cD, mask, out, 128);
}

// round 9
// speedup vs baseline: 1.3500x; 1.3500x over previous
#include <cuda_runtime.h>
#include <cuda_bf16.h>
#include <math.h>
#include <cstdint>

#define NN 4096
#define DD 128
#define HH 4
#define NMID 9
#define PSTR 40  // bf16 elems per smem row (80B, ldmatrix conflict-free)

typedef unsigned long long u64;

// ===========================================================================
// PTX helpers (sm_80-class: compiles for plain sm_103)
// ===========================================================================
__device__ __forceinline__ uint32_t smem_u32(const void* p) {
    uint32_t a;
    asm("{ .reg .u64 t; cvta.to.shared.u64 t, %1; cvt.u32.u64 %0, t; }" : "=r"(a) : "l"(p));
    return a;
}
__device__ __forceinline__ void ldsm_x4(unsigned* r, uint32_t addr) {
    asm volatile("ldmatrix.sync.aligned.m8n8.x4.shared.b16 {%0,%1,%2,%3}, [%4];"
                 : "=r"(r[0]), "=r"(r[1]), "=r"(r[2]), "=r"(r[3]) : "r"(addr));
}
__device__ __forceinline__ void mma_bf16(float* d, const unsigned* a, const unsigned* b) {
    asm volatile(
        "mma.sync.aligned.m16n8k16.row.col.f32.bf16.bf16.f32 "
        "{%0,%1,%2,%3}, {%4,%5,%6,%7}, {%8,%9}, {%0,%1,%2,%3};"
        : "+f"(d[0]), "+f"(d[1]), "+f"(d[2]), "+f"(d[3])
        : "r"(a[0]), "r"(a[1]), "r"(a[2]), "r"(a[3]), "r"(b[0]), "r"(b[1]));
}
__device__ __forceinline__ void cp16(uint32_t dst, const void* src) {
    asm volatile("cp.async.ca.shared.global [%0], [%1], 16;" :: "r"(dst), "l"(src) : "memory");
}
#define CP_COMMIT() asm volatile("cp.async.commit_group;" ::: "memory")
#define CP_WAIT0()  asm volatile("cp.async.wait_group 0;" ::: "memory")

// ===========================================================================
// Scratch (device globals)
// ===========================================================================
__device__ __align__(16) float g_X0[NN * 512];
__device__ __align__(16) float g_X1[NN * 512];
__device__ __align__(16) float g_Wh[HH * NN * DD];
__device__ __align__(16) __nv_bfloat16 g_WhT_hi[HH * DD * NN];  // [h][n=128][k=4096]
__device__ __align__(16) __nv_bfloat16 g_WhT_lo[HH * DD * NN];
__device__ __align__(16) __nv_bfloat16 g_Xhi[NN * 512];
__device__ __align__(16) __nv_bfloat16 g_Xlo[NN * 512];
__device__ __align__(16) __nv_bfloat16 g_Wt_hi[HH * DD * 512];  // [h][n=128][k<=512]
__device__ __align__(16) __nv_bfloat16 g_Wt_lo[HH * DD * 512];
__device__ float g_f1[HH * NN];
__device__ float g_f2[HH * NN];
__device__ float g_f2max[HH];
__device__ __align__(16) float g_colB[HH * NN];
__device__ __align__(16) float g_colD[HH * NN];
__device__ unsigned g_mask[NN * 128];

// ===========================================================================
// adj > 0 -> bitmask
// ===========================================================================
__global__ void build_mask_kernel(const float* __restrict__ adj,
                                  unsigned* __restrict__ mask) {
    int i = blockIdx.x;
    int t = threadIdx.x;
    int lane = t & 31;
    const float* row = adj + (size_t)i * NN;
    for (int word = t >> 5; word < 128; word += 8) {
        float v = row[word * 32 + lane];
        unsigned b = __ballot_sync(0xffffffffu, v > 0.f);
        if (lane == 0) mask[i * 128 + word] = b;
    }
}

__global__ void hrc_kernel(const int* __restrict__ head, const int* __restrict__ rel,
                           const float* __restrict__ ee, const float* __restrict__ re,
                           float* __restrict__ out) {
    int i = blockIdx.x;
    int d = threadIdx.x;
    out[(size_t)i * 128 + d] =
        ee[(size_t)head[i] * 128 + d] + re[(size_t)rel[i] * 128 + d];
}

// ===========================================================================
// fp32 -> bf16 hi/lo split (flat)
// ===========================================================================
__global__ void split_kernel(const float* __restrict__ src,
                             __nv_bfloat16* __restrict__ hi,
                             __nv_bfloat16* __restrict__ lo, int n) {
    int i = blockIdx.x * 256 + threadIdx.x;
    if (i < n) {
        float v = src[i];
        __nv_bfloat16 h = __float2bfloat16(v);
        hi[i] = h;
        lo[i] = __float2bfloat16(v - __bfloat162float(h));
    }
}

// ===========================================================================
// transpose + split: src fp32 [h][kdim][128] -> hi/lo bf16 [h][128][kdim]
// grid (kdim/32, 4, H)
// ===========================================================================
__global__ void wt_split_kernel(const float* __restrict__ src,
                                __nv_bfloat16* __restrict__ dhi,
                                __nv_bfloat16* __restrict__ dlo, int kdim) {
    int h = blockIdx.z;
    int kbase = blockIdx.x * 32;
    int nbase = blockIdx.y * 32;
    __shared__ float ts[32][33];
    const float* sp = src + (size_t)h * kdim * 128;
    int t = threadIdx.x;
#pragma unroll
    for (int l = 0; l < 4; l++) {
        int e = t + l * 256;
        int r = e >> 5, c = e & 31;
        ts[r][c] = sp[(size_t)(kbase + r) * 128 + nbase + c];
    }
    __syncthreads();
#pragma unroll
    for (int l = 0; l < 4; l++) {
        int e = t + l * 256;
        int r = e >> 5, c = e & 31;  // r = n-local, c = k-local
        float v = ts[c][r];
        __nv_bfloat16 hi = __float2bfloat16(v);
        __nv_bfloat16 lo = __float2bfloat16(v - __bfloat162float(hi));
        size_t o = (size_t)(h * 128 + nbase + r) * kdim + kbase + c;
        dhi[o] = hi;
        dlo[o] = lo;
    }
}

// ===========================================================================
// Tensorized Wh = X @ W : A = Xhi/lo [m][k], B = Wt hi/lo [h][n=128][k=Fin]
// CTA: 64m x 128n, grid (64, H).
// ===========================================================================
__global__ void __launch_bounds__(256)
gemm_mma_kernel(const __nv_bfloat16* __restrict__ Xhi, const __nv_bfloat16* __restrict__ Xlo,
                const __nv_bfloat16* __restrict__ WtHi, const __nv_bfloat16* __restrict__ WtLo,
                float* __restrict__ Wh, int Fin) {
    __shared__ __align__(16) __nv_bfloat16 Ahi[64][PSTR];
    __shared__ __align__(16) __nv_bfloat16 Alo[64][PSTR];
    __shared__ __align__(16) __nv_bfloat16 Bhi[128][PSTR];
    __shared__ __align__(16) __nv_bfloat16 Blo[128][PSTR];

    int h = blockIdx.y;
    int row0 = blockIdx.x * 64;
    int t = threadIdx.x, wid = t >> 5, lane = t & 31;
    int wr = wid & 3, wc = wid >> 2;
    const __nv_bfloat16* Wth = WtHi + (size_t)h * 128 * Fin;
    const __nv_bfloat16* Wtl = WtLo + (size_t)h * 128 * Fin;
    float* outp = Wh + (size_t)h * NN * 128;

    uint32_t sAhi = smem_u32(Ahi), sAlo = smem_u32(Alo);
    uint32_t sBhi = smem_u32(Bhi), sBlo = smem_u32(Blo);
    float d[8][4] = {};

    uint32_t a_off = (uint32_t)(wr * 16 + ((lane >> 3) & 1) * 8 + (lane & 7)) * (PSTR * 2)
                   + (uint32_t)((lane >> 4) * 8) * 2;
    uint32_t b_roff = (uint32_t)(wc * 64 + (lane >> 4) * 8 + (lane & 7)) * (PSTR * 2);
    uint32_t b_koff = (uint32_t)(((lane >> 3) & 1) * 8) * 2;

    for (int k0 = 0; k0 < Fin; k0 += 32) {
        __syncthreads();
        {
            int m = t >> 2, q = t & 3;
            size_t go = (size_t)(row0 + m) * Fin + k0 + q * 8;
            *(uint4*)&Ahi[m][q * 8] = *(const uint4*)(Xhi + go);
            *(uint4*)&Alo[m][q * 8] = *(const uint4*)(Xlo + go);
        }
#pragma unroll
        for (int l = 0; l < 2; l++) {
            int idx = t + l * 256;
            int n = idx >> 2, q = idx & 3;
            size_t go = (size_t)n * Fin + k0 + q * 8;
            *(uint4*)&Bhi[n][q * 8] = *(const uint4*)(Wth + go);
            *(uint4*)&Blo[n][q * 8] = *(const uint4*)(Wtl + go);
        }
        __syncthreads();
#pragma unroll
        for (int s = 0; s < 2; s++) {
            unsigned ah[4], al[4];
            ldsm_x4(ah, sAhi + a_off + s * 32);
            ldsm_x4(al, sAlo + a_off + s * 32);
#pragma unroll
            for (int pp = 0; pp < 4; pp++) {
                unsigned bh[4], bl[4];
                uint32_t boff = b_roff + (uint32_t)(pp * 16) * (PSTR * 2) + b_koff + s * 32;
                ldsm_x4(bh, sBhi + boff);
                ldsm_x4(bl, sBlo + boff);
                mma_bf16(d[2 * pp],     ah, bh);
                mma_bf16(d[2 * pp + 1], ah, bh + 2);
                mma_bf16(d[2 * pp],     ah, bl);
                mma_bf16(d[2 * pp + 1], ah, bl + 2);
                mma_bf16(d[2 * pp],     al, bh);
                mma_bf16(d[2 * pp + 1], al, bh + 2);
            }
        }
    }
    int r0 = row0 + wr * 16 + (lane >> 2);
    int cbase = wc * 64 + (lane & 3) * 2;
#pragma unroll
    for (int nt = 0; nt < 8; nt++) {
        int col = cbase + nt * 8;
        *(float2*)&outp[(size_t)r0 * 128 + col] = make_float2(d[nt][0], d[nt][1]);
        *(float2*)&outp[(size_t)(r0 + 8) * 128 + col] = make_float2(d[nt][2], d[nt][3]);
    }
}

// ===========================================================================
// f1/f2
// ===========================================================================
__global__ void compute_f_kernel(const float* __restrict__ Wh, const float* __restrict__ A,
                                 float* __restrict__ f1, float* __restrict__ f2) {
    int h = blockIdx.y;
    int warp = threadIdx.x >> 5, lane = threadIdx.x & 31;
    int i = blockIdx.x * 8 + warp;
    const float* row = Wh + ((size_t)h * NN + i) * 128;
    const float* a = A + h * 256;
    float s1 = 0.f, s2 = 0.f;
#pragma unroll
    for (int d = lane; d < 128; d += 32) {
        float v = row[d];
        s1 += v * a[d];
        s2 += v * a[128 + d];
    }
#pragma unroll
    for (int o = 16; o; o >>= 1) {
        s1 += __shfl_xor_sync(0xffffffffu, s1, o);
        s2 += __shfl_xor_sync(0xffffffffu, s2, o);
    }
    if (lane == 0) {
        f1[h * NN + i] = s1;
        f2[h * NN + i] = s2;
    }
}

// ===========================================================================
// per-head max of f2 (for softmax stability bound)
// ===========================================================================
__global__ void f2max_kernel(const float* __restrict__ f2, float* __restrict__ fmax) {
    int h = blockIdx.x;
    __shared__ float red[32];
    float m = -1e30f;
    for (int i = threadIdx.x; i < NN; i += 1024)
        m = fmaxf(m, f2[h * NN + i]);
#pragma unroll
    for (int o = 16; o; o >>= 1) m = fmaxf(m, __shfl_xor_sync(0xffffffffu, m, o));
    if ((threadIdx.x & 31) == 0) red[threadIdx.x >> 5] = m;
    __syncthreads();
    if (threadIdx.x < 32) {
        m = red[threadIdx.x];
#pragma unroll
        for (int o = 16; o; o >>= 1) m = fmaxf(m, __shfl_xor_sync(0xffffffffu, m, o));
        if (threadIdx.x == 0) fmax[h] = m;
    }
}

// ===========================================================================
// colB = exp(f2), colD = exp(0.2 f2)
// ===========================================================================
__global__ void prep_vec_kernel(const float* __restrict__ f2,
                                float* __restrict__ colB, float* __restrict__ colD) {
    int h = blockIdx.y;
    int i = blockIdx.x * 256 + threadIdx.x;
    int idx = h * NN + i;
    float b = f2[idx];
    colB[idx] = __expf(b);
    colD[idx] = __expf(0.2f * b);
}

// ===========================================================================
// Pipelined mma.sync attention. CTA 64m x 128n, grid (64, H).
// Unnormalized P (on-the-fly bf16 hi/lo) @ WhT; row sums accumulated during
// P-gen; epilogue divides by row sum then applies elu.
// smem layout (bytes):
//   P[buf][hl]: (buf*2+hl)*5120        (64 rows x 80B)   total 20480
//   B[buf][hl]: 20480+(buf*2+hl)*10240 (128 rows x 80B)  total 40960
//   rowsum:     61440 (64 floats)
// ===========================================================================
#define ATT_SMEM 61696

__global__ void __launch_bounds__(256)
attn_mma_kernel(const __nv_bfloat16* __restrict__ WhT_hi,
                const __nv_bfloat16* __restrict__ WhT_lo,
                const float* __restrict__ f1v, const float* __restrict__ f2max,
                const float* __restrict__ colB, const float* __restrict__ colD,
                const unsigned* __restrict__ mask,
                float* __restrict__ out, int out_stride) {
    extern __shared__ __align__(16) char smem[];
    uint32_t sb = smem_u32(smem);
    const uint32_t sP = sb;
    const uint32_t sB = sb + 20480;
    float* rsum = (float*)(smem + 61440);

    int h = blockIdx.y;
    int row0 = blockIdx.x * 64;
    int hbase = h * NN;
    int t = threadIdx.x, wid = t >> 5, lane = t & 31;
    int wr = wid & 3, wc = wid >> 2;

    const __nv_bfloat16* Whh = WhT_hi + (size_t)(h * 128) * NN;
    const __nv_bfloat16* Whl = WhT_lo + (size_t)(h * 128) * NN;

    // P-gen role: thread covers row pr (0..63), k-octet kq (0..3) of each chunk
    int pr = t >> 2, kq = t & 3;
    float f1r = f1v[hbase + row0 + pr];
    float mF2 = f2max[h];
    // stability bound: m = leaky(f1 + maxF2) >= masked max of leaky(f1+f2)
    float xm = f1r + mF2;
    float m = xm > 0.f ? xm : 0.2f * xm;
    float Ar = __expf(f1r - m);
    float Cr = __expf(0.2f * f1r - m);
    float psum = 0.f;

    const unsigned* mrow = mask + (size_t)(row0 + pr) * 128;
    const float* cBp = colB + hbase;
    const float* cDp = colD + hbase;

    // ldmatrix lane addresses (bytes)
    uint32_t a_off = (uint32_t)(wr * 16 + ((lane >> 3) & 1) * 8 + (lane & 7)) * (PSTR * 2)
                   + (uint32_t)((lane >> 4) * 8) * 2;
    uint32_t b_roff = (uint32_t)(wc * 64 + (lane >> 4) * 8 + (lane & 7)) * (PSTR * 2);
    uint32_t b_koff = (uint32_t)(((lane >> 3) & 1) * 8) * 2;

    float d[8][4] = {};

    auto stage = [&](int c, int buf) {
#pragma unroll
        for (int l = 0; l < 2; l++) {
            int idx = t + l * 256;
            int n = idx >> 2, q = idx & 3;
            size_t go = (size_t)n * NN + c * 32 + q * 8;
            cp16(sB + (uint32_t)(buf * 2 + 0) * 10240 + n * 80 + q * 16, Whh + go);
            cp16(sB + (uint32_t)(buf * 2 + 1) * 10240 + n * 80 + q * 16, Whl + go);
        }
        CP_COMMIT();
    };
    auto pgen = [&](int c, int buf) {
        int kb = c * 32 + kq * 8;
        unsigned w8 = mrow[c] >> (kq * 8);
        float4 b0 = *(const float4*)(cBp + kb);
        float4 b1 = *(const float4*)(cBp + kb + 4);
        float4 d0 = *(const float4*)(cDp + kb);
        float4 d1 = *(const float4*)(cDp + kb + 4);
        float p[8];
        p[0] = (w8 & 1u)   ? fmaxf(Ar * b0.x, Cr * d0.x) : 0.f;
        p[1] = (w8 & 2u)   ? fmaxf(Ar * b0.y, Cr * d0.y) : 0.f;
        p[2] = (w8 & 4u)   ? fmaxf(Ar * b0.z, Cr * d0.z) : 0.f;
        p[3] = (w8 & 8u)   ? fmaxf(Ar * b0.w, Cr * d0.w) : 0.f;
        p[4] = (w8 & 16u)  ? fmaxf(Ar * b1.x, Cr * d1.x) : 0.f;
        p[5] = (w8 & 32u)  ? fmaxf(Ar * b1.y, Cr * d1.y) : 0.f;
        p[6] = (w8 & 64u)  ? fmaxf(Ar * b1.z, Cr * d1.z) : 0.f;
        p[7] = (w8 & 128u) ? fmaxf(Ar * b1.w, Cr * d1.w) : 0.f;
        psum += ((p[0] + p[1]) + (p[2] + p[3])) + ((p[4] + p[5]) + (p[6] + p[7]));
        uint4 uh, ul;
        unsigned* ph = &uh.x;
        unsigned* pl = &ul.x;
#pragma unroll
        for (int j = 0; j < 4; j++) {
            __nv_bfloat162 h2 = __floats2bfloat162_rn(p[2 * j], p[2 * j + 1]);
            float r0 = p[2 * j] - __bfloat162float(h2.x);
            float r1 = p[2 * j + 1] - __bfloat162float(h2.y);
            __nv_bfloat162 l2 = __floats2bfloat162_rn(r0, r1);
            ph[j] = *(unsigned*)&h2;
            pl[j] = *(unsigned*)&l2;
        }
        *(uint4*)(smem + (buf * 2 + 0) * 5120 + pr * 80 + kq * 16) = uh;
        *(uint4*)(smem + (buf * 2 + 1) * 5120 + pr * 80 + kq * 16) = ul;
    };

    // prologue
    stage(0, 0);
    pgen(0, 0);

    for (int c = 0; c < 128; c++) {
        int buf = c & 1;
        CP_WAIT0();
        __syncthreads();     // publish B(c), P(c); all readers of buf^1 done
        if (c + 1 < 128) {
            stage(c + 1, buf ^ 1);   // overlaps with mma below
            pgen(c + 1, buf ^ 1);
        }
        uint32_t pH = sP + (uint32_t)(buf * 2 + 0) * 5120;
        uint32_t pL = sP + (uint32_t)(buf * 2 + 1) * 5120;
        uint32_t bH = sB + (uint32_t)(buf * 2 + 0) * 10240;
        uint32_t bL = sB + (uint32_t)(buf * 2 + 1) * 10240;
#pragma unroll
        for (int s = 0; s < 2; s++) {
            unsigned ah[4], al[4];
            ldsm_x4(ah, pH + a_off + s * 32);
            ldsm_x4(al, pL + a_off + s * 32);
#pragma unroll
            for (int pp = 0; pp < 4; pp++) {
                unsigned bh[4], bl[4];
                uint32_t boff = b_roff + (uint32_t)(pp * 16) * (PSTR * 2) + b_koff + s * 32;
                ldsm_x4(bh, bH + boff);
                ldsm_x4(bl, bL + boff);
                mma_bf16(d[2 * pp],     ah, bh);
                mma_bf16(d[2 * pp + 1], ah, bh + 2);
                mma_bf16(d[2 * pp],     ah, bl);
                mma_bf16(d[2 * pp + 1], ah, bl + 2);
                mma_bf16(d[2 * pp],     al, bh);
                mma_bf16(d[2 * pp + 1], al, bh + 2);
            }
        }
    }

    // row-sum reduction: threads 4pr..4pr+3 (same warp) hold partials
    psum += __shfl_xor_sync(0xffffffffu, psum, 1);
    psum += __shfl_xor_sync(0xffffffffu, psum, 2);
    if (kq == 0) rsum[pr] = psum;
    __syncthreads();

    // epilogue: normalize + elu + write
    int rloc = wr * 16 + (lane >> 2);
    float inv0 = 1.f / rsum[rloc];
    float inv1 = 1.f / rsum[rloc + 8];
    int r0 = row0 + rloc;
    int cbase = h * 128 + wc * 64 + (lane & 3) * 2;
#pragma unroll
    for (int nt = 0; nt < 8; nt++) {
        int col = cbase + nt * 8;
        float v0 = d[nt][0] * inv0, v1 = d[nt][1] * inv0;
        float v2 = d[nt][2] * inv1, v3 = d[nt][3] * inv1;
        v0 = v0 > 0.f ? v0 : expm1f(v0);
        v1 = v1 > 0.f ? v1 : expm1f(v1);
        v2 = v2 > 0.f ? v2 : expm1f(v2);
        v3 = v3 > 0.f ? v3 : expm1f(v3);
        *(float2*)&out[(size_t)r0 * out_stride + col] = make_float2(v0, v1);
        *(float2*)&out[(size_t)(r0 + 8) * out_stride + col] = make_float2(v2, v3);
    }
}

// ===========================================================================
extern "C" void kernel_launch(void* const* d_in, const int* in_sizes, int n_in,
                              void* d_out, int out_size) {
    const int* head = (const int*)d_in[0];
    const int* rel = (const int*)d_in[1];
    const float* adj = (const float*)d_in[2];
    const float* ee = (const float*)d_in[3];
    const float* re = (const float*)d_in[4];
    const float* W0 = (const float*)d_in[5];
    const float* a0 = (const float*)d_in[6];
    const float* Wm = (const float*)d_in[7];
    const float* am = (const float*)d_in[8];
    const float* Wo = (const float*)d_in[9];
    const float* ao = (const float*)d_in[10];
    float* out = (float*)d_out;

    float *X0, *X1, *Wh, *f1, *f2, *fmax, *cB, *cD;
    __nv_bfloat16 *WhTh, *WhTl, *Xhi, *Xlo, *Wth, *Wtl;
    unsigned* mask;
    cudaGetSymbolAddress((void**)&X0, g_X0);
    cudaGetSymbolAddress((void**)&X1, g_X1);
    cudaGetSymbolAddress((void**)&Wh, g_Wh);
    cudaGetSymbolAddress((void**)&f1, g_f1);
    cudaGetSymbolAddress((void**)&f2, g_f2);
    cudaGetSymbolAddress((void**)&fmax, g_f2max);
    cudaGetSymbolAddress((void**)&cB, g_colB);
    cudaGetSymbolAddress((void**)&cD, g_colD);
    cudaGetSymbolAddress((void**)&WhTh, g_WhT_hi);
    cudaGetSymbolAddress((void**)&WhTl, g_WhT_lo);
    cudaGetSymbolAddress((void**)&Xhi, g_Xhi);
    cudaGetSymbolAddress((void**)&Xlo, g_Xlo);
    cudaGetSymbolAddress((void**)&Wth, g_Wt_hi);
    cudaGetSymbolAddress((void**)&Wtl, g_Wt_lo);
    cudaGetSymbolAddress((void**)&mask, g_mask);

    cudaFuncSetAttribute(attn_mma_kernel, cudaFuncAttributeMaxDynamicSharedMemorySize, ATT_SMEM);

    build_mask_kernel<<<NN, 256>>>(adj, mask);
    hrc_kernel<<<NN, 128>>>(head, rel, ee, re, out + (size_t)NN * 128);

    // ---- layer 0: Fin = 128, X = entity_emb ----
    split_kernel<<<(NN * 128 + 255) / 256, 256>>>(ee, Xhi, Xlo, NN * 128);
    wt_split_kernel<<<dim3(4, 4, HH), 256>>>(W0, Wth, Wtl, 128);
    gemm_mma_kernel<<<dim3(64, HH), 256>>>(Xhi, Xlo, Wth, Wtl, Wh, 128);
    compute_f_kernel<<<dim3(512, HH), 256>>>(Wh, a0, f1, f2);
    f2max_kernel<<<HH, 1024>>>(f2, fmax);
    prep_vec_kernel<<<dim3(16, HH), 256>>>(f2, cB, cD);
    wt_split_kernel<<<dim3(128, 4, HH), 256>>>(Wh, WhTh, WhTl, NN);
    attn_mma_kernel<<<dim3(64, HH), 256, ATT_SMEM>>>(WhTh, WhTl, f1, fmax, cB, cD, mask, X0, 512);

    // ---- 9 middle layers: Fin = 512 ----
    float* cur = X0;
    float* nxt = X1;
    for (int l = 0; l < NMID; l++) {
        split_kernel<<<(NN * 512 + 255) / 256, 256>>>(cur, Xhi, Xlo, NN * 512);
        wt_split_kernel<<<dim3(16, 4, HH), 256>>>(Wm + (size_t)l * HH * 512 * 128, Wth, Wtl, 512);
        gemm_mma_kernel<<<dim3(64, HH), 256>>>(Xhi, Xlo, Wth, Wtl, Wh, 512);
        compute_f_kernel<<<dim3(512, HH), 256>>>(Wh, am + (size_t)l * HH * 256, f1, f2);
        f2max_kernel<<<HH, 1024>>>(f2, fmax);
        prep_vec_kernel<<<dim3(16, HH), 256>>>(f2, cB, cD);
        wt_split_kernel<<<dim3(128, 4, HH), 256>>>(Wh, WhTh, WhTl, NN);
        attn_mma_kernel<<<dim3(64, HH), 256, ATT_SMEM>>>(WhTh, WhTl, f1, fmax, cB, cD, mask, nxt, 512);
        float* tmp = cur; cur = nxt; nxt = tmp;
    }

    // ---- output layer: 1 head, Fin = 512 ----
    split_kernel<<<(NN * 512 + 255) / 256, 256>>>(cur, Xhi, Xlo, NN * 512);
    wt_split_kernel<<<dim3(16, 4, 1), 256>>>(Wo, Wth, Wtl, 512);
    gemm_mma_kernel<<<dim3(64, 1), 256>>>(Xhi, Xlo, Wth, Wtl, Wh, 512);
    compute_f_kernel<<<dim3(512, 1), 256>>>(Wh, ao, f1, f2);
    f2max_kernel<<<1, 1024>>>(f2, fmax);
    prep_vec_kernel<<<dim3(16, 1), 256>>>(f2, cB, cD);
    wt_split_kernel<<<dim3(128, 4, 1), 256>>>(Wh, WhTh, WhTl, NN);
    attn_mma_kernel<<<dim3(64, 1), 256, ATT_SMEM>>>(WhTh, WhTl, f1, fmax, cB, cD, mask, out, 128);
}

// round 10
// speedup vs baseline: 1.5510x; 1.1488x over previous
#include <cuda_runtime.h>
#include <cuda_bf16.h>
#include <cuda_fp16.h>
#include <math.h>
#include <cstdint>

#define NN 4096
#define DD 128
#define HH 4
#define NMID 9
#define PSTR 40  // 16-bit elems per smem row (80B, ldmatrix conflict-free)

typedef unsigned long long u64;

// ===========================================================================
// PTX helpers (sm_80-class: compiles for plain sm_103)
// ===========================================================================
__device__ __forceinline__ uint32_t smem_u32(const void* p) {
    uint32_t a;
    asm("{ .reg .u64 t; cvta.to.shared.u64 t, %1; cvt.u32.u64 %0, t; }" : "=r"(a) : "l"(p));
    return a;
}
__device__ __forceinline__ void ldsm_x4(unsigned* r, uint32_t addr) {
    asm volatile("ldmatrix.sync.aligned.m8n8.x4.shared.b16 {%0,%1,%2,%3}, [%4];"
                 : "=r"(r[0]), "=r"(r[1]), "=r"(r[2]), "=r"(r[3]) : "r"(addr));
}
__device__ __forceinline__ void mma_bf16(float* d, const unsigned* a, const unsigned* b) {
    asm volatile(
        "mma.sync.aligned.m16n8k16.row.col.f32.bf16.bf16.f32 "
        "{%0,%1,%2,%3}, {%4,%5,%6,%7}, {%8,%9}, {%0,%1,%2,%3};"
        : "+f"(d[0]), "+f"(d[1]), "+f"(d[2]), "+f"(d[3])
        : "r"(a[0]), "r"(a[1]), "r"(a[2]), "r"(a[3]), "r"(b[0]), "r"(b[1]));
}
__device__ __forceinline__ void mma_f16(float* d, const unsigned* a, const unsigned* b) {
    asm volatile(
        "mma.sync.aligned.m16n8k16.row.col.f32.f16.f16.f32 "
        "{%0,%1,%2,%3}, {%4,%5,%6,%7}, {%8,%9}, {%0,%1,%2,%3};"
        : "+f"(d[0]), "+f"(d[1]), "+f"(d[2]), "+f"(d[3])
        : "r"(a[0]), "r"(a[1]), "r"(a[2]), "r"(a[3]), "r"(b[0]), "r"(b[1]));
}
__device__ __forceinline__ void cp16(uint32_t dst, const void* src) {
    asm volatile("cp.async.ca.shared.global [%0], [%1], 16;" :: "r"(dst), "l"(src) : "memory");
}
#define CP_COMMIT() asm volatile("cp.async.commit_group;" ::: "memory")
#define CP_WAIT0()  asm volatile("cp.async.wait_group 0;" ::: "memory")

// ===========================================================================
// Scratch (device globals)
// ===========================================================================
__device__ __align__(16) float g_Wh[HH * NN * DD];
__device__ __align__(16) __half g_WhT_hi[HH * DD * NN];  // [h][n=128][k=4096] fp16
__device__ __align__(16) __half g_WhT_lo[HH * DD * NN];
__device__ __align__(16) __nv_bfloat16 g_Xhi[NN * 512];
__device__ __align__(16) __nv_bfloat16 g_Xlo[NN * 512];
__device__ __align__(16) __nv_bfloat16 g_Wt_hi[HH * DD * 512];
__device__ __align__(16) __nv_bfloat16 g_Wt_lo[HH * DD * 512];
__device__ float g_f1[HH * NN];
__device__ float g_f2[HH * NN];
__device__ float g_f2max[HH];
__device__ __align__(16) float g_colB[HH * NN];
__device__ __align__(16) float g_colD[HH * NN];
__device__ unsigned g_mask[NN * 128];

// ===========================================================================
// adj > 0 -> bitmask
// ===========================================================================
__global__ void build_mask_kernel(const float* __restrict__ adj,
                                  unsigned* __restrict__ mask) {
    int i = blockIdx.x;
    int t = threadIdx.x;
    int lane = t & 31;
    const float* row = adj + (size_t)i * NN;
    for (int word = t >> 5; word < 128; word += 8) {
        float v = row[word * 32 + lane];
        unsigned b = __ballot_sync(0xffffffffu, v > 0.f);
        if (lane == 0) mask[i * 128 + word] = b;
    }
}

__global__ void hrc_kernel(const int* __restrict__ head, const int* __restrict__ rel,
                           const float* __restrict__ ee, const float* __restrict__ re,
                           float* __restrict__ out) {
    int i = blockIdx.x;
    int d = threadIdx.x;
    out[(size_t)i * 128 + d] =
        ee[(size_t)head[i] * 128 + d] + re[(size_t)rel[i] * 128 + d];
}

// ===========================================================================
// fp32 -> bf16 hi/lo split (flat) — only used for layer-0 input (ee)
// ===========================================================================
__global__ void split_kernel(const float* __restrict__ src,
                             __nv_bfloat16* __restrict__ hi,
                             __nv_bfloat16* __restrict__ lo, int n) {
    int i = blockIdx.x * 256 + threadIdx.x;
    if (i < n) {
        float v = src[i];
        __nv_bfloat16 h = __float2bfloat16(v);
        hi[i] = h;
        lo[i] = __float2bfloat16(v - __bfloat162float(h));
    }
}

// ===========================================================================
// transpose + split bf16: weights [h][kdim][128] -> [h][128][kdim]
// ===========================================================================
__global__ void wt_split_kernel(const float* __restrict__ src,
                                __nv_bfloat16* __restrict__ dhi,
                                __nv_bfloat16* __restrict__ dlo, int kdim) {
    int h = blockIdx.z;
    int kbase = blockIdx.x * 32;
    int nbase = blockIdx.y * 32;
    __shared__ float ts[32][33];
    const float* sp = src + (size_t)h * kdim * 128;
    int t = threadIdx.x;
#pragma unroll
    for (int l = 0; l < 4; l++) {
        int e = t + l * 256;
        int r = e >> 5, c = e & 31;
        ts[r][c] = sp[(size_t)(kbase + r) * 128 + nbase + c];
    }
    __syncthreads();
#pragma unroll
    for (int l = 0; l < 4; l++) {
        int e = t + l * 256;
        int r = e >> 5, c = e & 31;
        float v = ts[c][r];
        __nv_bfloat16 hi = __float2bfloat16(v);
        __nv_bfloat16 lo = __float2bfloat16(v - __bfloat162float(hi));
        size_t o = (size_t)(h * 128 + nbase + r) * kdim + kbase + c;
        dhi[o] = hi;
        dlo[o] = lo;
    }
}

// ===========================================================================
// transpose + split fp16: Wh [h][4096][128] -> WhT [h][128][4096]
// ===========================================================================
__global__ void wt_split_f16_kernel(const float* __restrict__ src,
                                    __half* __restrict__ dhi,
                                    __half* __restrict__ dlo, int kdim) {
    int h = blockIdx.z;
    int kbase = blockIdx.x * 32;
    int nbase = blockIdx.y * 32;
    __shared__ float ts[32][33];
    const float* sp = src + (size_t)h * kdim * 128;
    int t = threadIdx.x;
#pragma unroll
    for (int l = 0; l < 4; l++) {
        int e = t + l * 256;
        int r = e >> 5, c = e & 31;
        ts[r][c] = sp[(size_t)(kbase + r) * 128 + nbase + c];
    }
    __syncthreads();
#pragma unroll
    for (int l = 0; l < 4; l++) {
        int e = t + l * 256;
        int r = e >> 5, c = e & 31;
        float v = ts[c][r];
        __half hi = __float2half_rn(v);
        __half lo = __float2half_rn(v - __half2float(hi));
        size_t o = (size_t)(h * 128 + nbase + r) * kdim + kbase + c;
        dhi[o] = hi;
        dlo[o] = lo;
    }
}

// ===========================================================================
// Tensorized Wh = X @ W : A = Xhi/lo bf16 [m][k], B = Wt bf16 [h][128][Fin]
// CTA: 64m x 128n, grid (64, H). 3-pass split.
// ===========================================================================
__global__ void __launch_bounds__(256)
gemm_mma_kernel(const __nv_bfloat16* __restrict__ Xhi, const __nv_bfloat16* __restrict__ Xlo,
                const __nv_bfloat16* __restrict__ WtHi, const __nv_bfloat16* __restrict__ WtLo,
                float* __restrict__ Wh, int Fin) {
    __shared__ __align__(16) __nv_bfloat16 Ahi[64][PSTR];
    __shared__ __align__(16) __nv_bfloat16 Alo[64][PSTR];
    __shared__ __align__(16) __nv_bfloat16 Bhi[128][PSTR];
    __shared__ __align__(16) __nv_bfloat16 Blo[128][PSTR];

    int h = blockIdx.y;
    int row0 = blockIdx.x * 64;
    int t = threadIdx.x, wid = t >> 5, lane = t & 31;
    int wr = wid & 3, wc = wid >> 2;
    const __nv_bfloat16* Wth = WtHi + (size_t)h * 128 * Fin;
    const __nv_bfloat16* Wtl = WtLo + (size_t)h * 128 * Fin;
    float* outp = Wh + (size_t)h * NN * 128;

    uint32_t sAhi = smem_u32(Ahi), sAlo = smem_u32(Alo);
    uint32_t sBhi = smem_u32(Bhi), sBlo = smem_u32(Blo);
    float d[8][4] = {};

    uint32_t a_off = (uint32_t)(wr * 16 + ((lane >> 3) & 1) * 8 + (lane & 7)) * (PSTR * 2)
                   + (uint32_t)((lane >> 4) * 8) * 2;
    uint32_t b_roff = (uint32_t)(wc * 64 + (lane >> 4) * 8 + (lane & 7)) * (PSTR * 2);
    uint32_t b_koff = (uint32_t)(((lane >> 3) & 1) * 8) * 2;

    for (int k0 = 0; k0 < Fin; k0 += 32) {
        __syncthreads();
        {
            int m = t >> 2, q = t & 3;
            size_t go = (size_t)(row0 + m) * Fin + k0 + q * 8;
            *(uint4*)&Ahi[m][q * 8] = *(const uint4*)(Xhi + go);
            *(uint4*)&Alo[m][q * 8] = *(const uint4*)(Xlo + go);
        }
#pragma unroll
        for (int l = 0; l < 2; l++) {
            int idx = t + l * 256;
            int n = idx >> 2, q = idx & 3;
            size_t go = (size_t)n * Fin + k0 + q * 8;
            *(uint4*)&Bhi[n][q * 8] = *(const uint4*)(Wth + go);
            *(uint4*)&Blo[n][q * 8] = *(const uint4*)(Wtl + go);
        }
        __syncthreads();
#pragma unroll
        for (int s = 0; s < 2; s++) {
            unsigned ah[4], al[4];
            ldsm_x4(ah, sAhi + a_off + s * 32);
            ldsm_x4(al, sAlo + a_off + s * 32);
#pragma unroll
            for (int pp = 0; pp < 4; pp++) {
                unsigned bh[4], bl[4];
                uint32_t boff = b_roff + (uint32_t)(pp * 16) * (PSTR * 2) + b_koff + s * 32;
                ldsm_x4(bh, sBhi + boff);
                ldsm_x4(bl, sBlo + boff);
                mma_bf16(d[2 * pp],     ah, bh);
                mma_bf16(d[2 * pp + 1], ah, bh + 2);
                mma_bf16(d[2 * pp],     ah, bl);
                mma_bf16(d[2 * pp + 1], ah, bl + 2);
                mma_bf16(d[2 * pp],     al, bh);
                mma_bf16(d[2 * pp + 1], al, bh + 2);
            }
        }
    }
    int r0 = row0 + wr * 16 + (lane >> 2);
    int cbase = wc * 64 + (lane & 3) * 2;
#pragma unroll
    for (int nt = 0; nt < 8; nt++) {
        int col = cbase + nt * 8;
        *(float2*)&outp[(size_t)r0 * 128 + col] = make_float2(d[nt][0], d[nt][1]);
        *(float2*)&outp[(size_t)(r0 + 8) * 128 + col] = make_float2(d[nt][2], d[nt][3]);
    }
}

// ===========================================================================
// f1/f2
// ===========================================================================
__global__ void compute_f_kernel(const float* __restrict__ Wh, const float* __restrict__ A,
                                 float* __restrict__ f1, float* __restrict__ f2) {
    int h = blockIdx.y;
    int warp = threadIdx.x >> 5, lane = threadIdx.x & 31;
    int i = blockIdx.x * 8 + warp;
    const float* row = Wh + ((size_t)h * NN + i) * 128;
    const float* a = A + h * 256;
    float s1 = 0.f, s2 = 0.f;
#pragma unroll
    for (int d = lane; d < 128; d += 32) {
        float v = row[d];
        s1 += v * a[d];
        s2 += v * a[128 + d];
    }
#pragma unroll
    for (int o = 16; o; o >>= 1) {
        s1 += __shfl_xor_sync(0xffffffffu, s1, o);
        s2 += __shfl_xor_sync(0xffffffffu, s2, o);
    }
    if (lane == 0) {
        f1[h * NN + i] = s1;
        f2[h * NN + i] = s2;
    }
}

// ===========================================================================
// per-head max of f2
// ===========================================================================
__global__ void f2max_kernel(const float* __restrict__ f2, float* __restrict__ fmax) {
    int h = blockIdx.x;
    __shared__ float red[32];
    float m = -1e30f;
    for (int i = threadIdx.x; i < NN; i += 1024)
        m = fmaxf(m, f2[h * NN + i]);
#pragma unroll
    for (int o = 16; o; o >>= 1) m = fmaxf(m, __shfl_xor_sync(0xffffffffu, m, o));
    if ((threadIdx.x & 31) == 0) red[threadIdx.x >> 5] = m;
    __syncthreads();
    if (threadIdx.x < 32) {
        m = red[threadIdx.x];
#pragma unroll
        for (int o = 16; o; o >>= 1) m = fmaxf(m, __shfl_xor_sync(0xffffffffu, m, o));
        if (threadIdx.x == 0) fmax[h] = m;
    }
}

// ===========================================================================
// colB = exp(f2), colD = exp(0.2 f2)
// ===========================================================================
__global__ void prep_vec_kernel(const float* __restrict__ f2,
                                float* __restrict__ colB, float* __restrict__ colD) {
    int h = blockIdx.y;
    int i = blockIdx.x * 256 + threadIdx.x;
    int idx = h * NN + i;
    float b = f2[idx];
    colB[idx] = __expf(b);
    colD[idx] = __expf(0.2f * b);
}

// ===========================================================================
// Pipelined mma.sync attention, 2-pass fp16. CTA 64m x 128n, grid (64, H).
// P single fp16 (on-the-fly, unnormalized), WhT fp16 hi/lo. Row sums in fp32.
// Epilogue normalizes, elu, and writes EITHER bf16 X hi/lo (intermediate) OR
// fp32 out (final layer).
// smem layout (bytes):
//   P[buf]:     buf*5120              (64 rows x 80B)   total 10240
//   B[buf][hl]: 10240+(buf*2+hl)*10240 (128 rows x 80B) total 40960
//   rowsum:     51200 (64 floats)
// ===========================================================================
#define ATT_SMEM 51456

__global__ void __launch_bounds__(256)
attn_mma_kernel(const __half* __restrict__ WhT_hi, const __half* __restrict__ WhT_lo,
                const float* __restrict__ f1v, const float* __restrict__ f2max,
                const float* __restrict__ colB, const float* __restrict__ colD,
                const unsigned* __restrict__ mask,
                float* __restrict__ out, int out_stride,
                __nv_bfloat16* __restrict__ xhi, __nv_bfloat16* __restrict__ xlo) {
    extern __shared__ __align__(16) char smem[];
    uint32_t sb = smem_u32(smem);
    const uint32_t sP = sb;
    const uint32_t sB = sb + 10240;
    float* rsum = (float*)(smem + 51200);

    int h = blockIdx.y;
    int row0 = blockIdx.x * 64;
    int hbase = h * NN;
    int t = threadIdx.x, wid = t >> 5, lane = t & 31;
    int wr = wid & 3, wc = wid >> 2;

    const __half* Whh = WhT_hi + (size_t)(h * 128) * NN;
    const __half* Whl = WhT_lo + (size_t)(h * 128) * NN;

    // P-gen role: thread covers row pr (0..63), k-octet kq (0..3)
    int pr = t >> 2, kq = t & 3;
    float f1r = f1v[hbase + row0 + pr];
    float mF2 = f2max[h];
    float xm = f1r + mF2;
    float m = xm > 0.f ? xm : 0.2f * xm;
    float Ar = __expf(f1r - m);
    float Cr = __expf(0.2f * f1r - m);
    float psum = 0.f;

    const unsigned* mrow = mask + (size_t)(row0 + pr) * 128;
    const float* cBp = colB + hbase;
    const float* cDp = colD + hbase;

    uint32_t a_off = (uint32_t)(wr * 16 + ((lane >> 3) & 1) * 8 + (lane & 7)) * (PSTR * 2)
                   + (uint32_t)((lane >> 4) * 8) * 2;
    uint32_t b_roff = (uint32_t)(wc * 64 + (lane >> 4) * 8 + (lane & 7)) * (PSTR * 2);
    uint32_t b_koff = (uint32_t)(((lane >> 3) & 1) * 8) * 2;

    float d[8][4] = {};

    auto stage = [&](int c, int buf) {
#pragma unroll
        for (int l = 0; l < 2; l++) {
            int idx = t + l * 256;
            int n = idx >> 2, q = idx & 3;
            size_t go = (size_t)n * NN + c * 32 + q * 8;
            cp16(sB + (uint32_t)(buf * 2 + 0) * 10240 + n * 80 + q * 16, Whh + go);
            cp16(sB + (uint32_t)(buf * 2 + 1) * 10240 + n * 80 + q * 16, Whl + go);
        }
        CP_COMMIT();
    };
    auto pgen = [&](int c, int buf) {
        int kb = c * 32 + kq * 8;
        unsigned w8 = mrow[c] >> (kq * 8);
        float4 b0 = *(const float4*)(cBp + kb);
        float4 b1 = *(const float4*)(cBp + kb + 4);
        float4 d0 = *(const float4*)(cDp + kb);
        float4 d1 = *(const float4*)(cDp + kb + 4);
        float p[8];
        p[0] = (w8 & 1u)   ? fmaxf(Ar * b0.x, Cr * d0.x) : 0.f;
        p[1] = (w8 & 2u)   ? fmaxf(Ar * b0.y, Cr * d0.y) : 0.f;
        p[2] = (w8 & 4u)   ? fmaxf(Ar * b0.z, Cr * d0.z) : 0.f;
        p[3] = (w8 & 8u)   ? fmaxf(Ar * b0.w, Cr * d0.w) : 0.f;
        p[4] = (w8 & 16u)  ? fmaxf(Ar * b1.x, Cr * d1.x) : 0.f;
        p[5] = (w8 & 32u)  ? fmaxf(Ar * b1.y, Cr * d1.y) : 0.f;
        p[6] = (w8 & 64u)  ? fmaxf(Ar * b1.z, Cr * d1.z) : 0.f;
        p[7] = (w8 & 128u) ? fmaxf(Ar * b1.w, Cr * d1.w) : 0.f;
        psum += ((p[0] + p[1]) + (p[2] + p[3])) + ((p[4] + p[5]) + (p[6] + p[7]));
        uint4 u;
        unsigned* ph = &u.x;
#pragma unroll
        for (int j = 0; j < 4; j++) {
            __half2 h2 = __floats2half2_rn(p[2 * j], p[2 * j + 1]);
            ph[j] = *(unsigned*)&h2;
        }
        *(uint4*)(smem + buf * 5120 + pr * 80 + kq * 16) = u;
    };

    // prologue
    stage(0, 0);
    pgen(0, 0);

    for (int c = 0; c < 128; c++) {
        int buf = c & 1;
        CP_WAIT0();
        __syncthreads();     // publish B(c), P(c); readers of buf^1 done
        if (c + 1 < 128) {
            stage(c + 1, buf ^ 1);   // overlaps with mma below
            pgen(c + 1, buf ^ 1);
        }
        uint32_t pH = sP + (uint32_t)buf * 5120;
        uint32_t bH = sB + (uint32_t)(buf * 2 + 0) * 10240;
        uint32_t bL = sB + (uint32_t)(buf * 2 + 1) * 10240;
#pragma unroll
        for (int s = 0; s < 2; s++) {
            unsigned ah[4];
            ldsm_x4(ah, pH + a_off + s * 32);
#pragma unroll
            for (int pp = 0; pp < 4; pp++) {
                unsigned bh[4], bl[4];
                uint32_t boff = b_roff + (uint32_t)(pp * 16) * (PSTR * 2) + b_koff + s * 32;
                ldsm_x4(bh, bH + boff);
                ldsm_x4(bl, bL + boff);
                mma_f16(d[2 * pp],     ah, bh);
                mma_f16(d[2 * pp + 1], ah, bh + 2);
                mma_f16(d[2 * pp],     ah, bl);
                mma_f16(d[2 * pp + 1], ah, bl + 2);
            }
        }
    }

    // row-sum reduction: threads 4pr..4pr+3 (same warp) hold partials
    psum += __shfl_xor_sync(0xffffffffu, psum, 1);
    psum += __shfl_xor_sync(0xffffffffu, psum, 2);
    if (kq == 0) rsum[pr] = psum;
    __syncthreads();

    // epilogue: normalize + elu + write
    int rloc = wr * 16 + (lane >> 2);
    float inv0 = 1.f / rsum[rloc];
    float inv1 = 1.f / rsum[rloc + 8];
    int r0 = row0 + rloc;
    int cbase = h * 128 + wc * 64 + (lane & 3) * 2;
#pragma unroll
    for (int nt = 0; nt < 8; nt++) {
        int col = cbase + nt * 8;
        float v0 = d[nt][0] * inv0, v1 = d[nt][1] * inv0;
        float v2 = d[nt][2] * inv1, v3 = d[nt][3] * inv1;
        v0 = v0 > 0.f ? v0 : expm1f(v0);
        v1 = v1 > 0.f ? v1 : expm1f(v1);
        v2 = v2 > 0.f ? v2 : expm1f(v2);
        v3 = v3 > 0.f ? v3 : expm1f(v3);
        if (xhi) {
            // intermediate layer: write bf16 hi/lo X directly (stride 512)
            __nv_bfloat16 h0 = __float2bfloat16(v0), h1 = __float2bfloat16(v1);
            __nv_bfloat16 h2 = __float2bfloat16(v2), h3 = __float2bfloat16(v3);
            __nv_bfloat16 l0 = __float2bfloat16(v0 - __bfloat162float(h0));
            __nv_bfloat16 l1 = __float2bfloat16(v1 - __bfloat162float(h1));
            __nv_bfloat16 l2 = __float2bfloat16(v2 - __bfloat162float(h2));
            __nv_bfloat16 l3 = __float2bfloat16(v3 - __bfloat162float(h3));
            *(__nv_bfloat162*)&xhi[(size_t)r0 * 512 + col] = __nv_bfloat162(h0, h1);
            *(__nv_bfloat162*)&xlo[(size_t)r0 * 512 + col] = __nv_bfloat162(l0, l1);
            *(__nv_bfloat162*)&xhi[(size_t)(r0 + 8) * 512 + col] = __nv_bfloat162(h2, h3);
            *(__nv_bfloat162*)&xlo[(size_t)(r0 + 8) * 512 + col] = __nv_bfloat162(l2, l3);
        } else {
            *(float2*)&out[(size_t)r0 * out_stride + col] = make_float2(v0, v1);
            *(float2*)&out[(size_t)(r0 + 8) * out_stride + col] = make_float2(v2, v3);
        }
    }
}

// ===========================================================================
extern "C" void kernel_launch(void* const* d_in, const int* in_sizes, int n_in,
                              void* d_out, int out_size) {
    const int* head = (const int*)d_in[0];
    const int* rel = (const int*)d_in[1];
    const float* adj = (const float*)d_in[2];
    const float* ee = (const float*)d_in[3];
    const float* re = (const float*)d_in[4];
    const float* W0 = (const float*)d_in[5];
    const float* a0 = (const float*)d_in[6];
    const float* Wm = (const float*)d_in[7];
    const float* am = (const float*)d_in[8];
    const float* Wo = (const float*)d_in[9];
    const float* ao = (const float*)d_in[10];
    float* out = (float*)d_out;

    float *Wh, *f1, *f2, *fmax, *cB, *cD;
    __half *WhTh, *WhTl;
    __nv_bfloat16 *Xhi, *Xlo, *Wth, *Wtl;
    unsigned* mask;
    cudaGetSymbolAddress((void**)&Wh, g_Wh);
    cudaGetSymbolAddress((void**)&f1, g_f1);
    cudaGetSymbolAddress((void**)&f2, g_f2);
    cudaGetSymbolAddress((void**)&fmax, g_f2max);
    cudaGetSymbolAddress((void**)&cB, g_colB);
    cudaGetSymbolAddress((void**)&cD, g_colD);
    cudaGetSymbolAddress((void**)&WhTh, g_WhT_hi);
    cudaGetSymbolAddress((void**)&WhTl, g_WhT_lo);
    cudaGetSymbolAddress((void**)&Xhi, g_Xhi);
    cudaGetSymbolAddress((void**)&Xlo, g_Xlo);
    cudaGetSymbolAddress((void**)&Wth, g_Wt_hi);
    cudaGetSymbolAddress((void**)&Wtl, g_Wt_lo);
    cudaGetSymbolAddress((void**)&mask, g_mask);

    cudaFuncSetAttribute(attn_mma_kernel, cudaFuncAttributeMaxDynamicSharedMemorySize, ATT_SMEM);

    build_mask_kernel<<<NN, 256>>>(adj, mask);
    hrc_kernel<<<NN, 128>>>(head, rel, ee, re, out + (size_t)NN * 128);

    // ---- layer 0: Fin = 128, X = entity_emb ----
    split_kernel<<<(NN * 128 + 255) / 256, 256>>>(ee, Xhi, Xlo, NN * 128);
    wt_split_kernel<<<dim3(4, 4, HH), 256>>>(W0, Wth, Wtl, 128);
    gemm_mma_kernel<<<dim3(64, HH), 256>>>(Xhi, Xlo, Wth, Wtl, Wh, 128);
    compute_f_kernel<<<dim3(512, HH), 256>>>(Wh, a0, f1, f2);
    f2max_kernel<<<HH, 1024>>>(f2, fmax);
    prep_vec_kernel<<<dim3(16, HH), 256>>>(f2, cB, cD);
    wt_split_f16_kernel<<<dim3(128, 4, HH), 256>>>(Wh, WhTh, WhTl, NN);
    attn_mma_kernel<<<dim3(64, HH), 256, ATT_SMEM>>>(WhTh, WhTl, f1, fmax, cB, cD, mask,
                                                     nullptr, 0, Xhi, Xlo);

    // ---- 9 middle layers: Fin = 512 ----
    for (int l = 0; l < NMID; l++) {
        wt_split_kernel<<<dim3(16, 4, HH), 256>>>(Wm + (size_t)l * HH * 512 * 128, Wth, Wtl, 512);
        gemm_mma_kernel<<<dim3(64, HH), 256>>>(Xhi, Xlo, Wth, Wtl, Wh, 512);
        compute_f_kernel<<<dim3(512, HH), 256>>>(Wh, am + (size_t)l * HH * 256, f1, f2);
        f2max_kernel<<<HH, 1024>>>(f2, fmax);
        prep_vec_kernel<<<dim3(16, HH), 256>>>(f2, cB, cD);
        wt_split_f16_kernel<<<dim3(128, 4, HH), 256>>>(Wh, WhTh, WhTl, NN);
        attn_mma_kernel<<<dim3(64, HH), 256, ATT_SMEM>>>(WhTh, WhTl, f1, fmax, cB, cD, mask,
                                                         nullptr, 0, Xhi, Xlo);
    }

    // ---- output layer: 1 head, Fin = 512 ----
    wt_split_kernel<<<dim3(16, 4, 1), 256>>>(Wo, Wth, Wtl, 512);
    gemm_mma_kernel<<<dim3(64, 1), 256>>>(Xhi, Xlo, Wth, Wtl, Wh, 512);
    compute_f_kernel<<<dim3(512, 1), 256>>>(Wh, ao, f1, f2);
    f2max_kernel<<<1, 1024>>>(f2, fmax);
    prep_vec_kernel<<<dim3(16, 1), 256>>>(f2, cB, cD);
    wt_split_f16_kernel<<<dim3(128, 4, 1), 256>>>(Wh, WhTh, WhTl, NN);
    attn_mma_kernel<<<dim3(64, 1), 256, ATT_SMEM>>>(WhTh, WhTl, f1, fmax, cB, cD, mask,
                                                    out, 128, nullptr, nullptr);
}

// round 11
// speedup vs baseline: 1.5970x; 1.0296x over previous
#include <cuda_runtime.h>
#include <cuda_bf16.h>
#include <cuda_fp16.h>
#include <math.h>
#include <cstdint>

#define NN 4096
#define DD 128
#define HH 4
#define NMID 9
#define PSTR 40  // 16-bit elems per smem row (80B, ldmatrix conflict-free)

typedef unsigned long long u64;

// ===========================================================================
// PTX helpers (sm_80-class: compiles for plain sm_103)
// ===========================================================================
__device__ __forceinline__ uint32_t smem_u32(const void* p) {
    uint32_t a;
    asm("{ .reg .u64 t; cvta.to.shared.u64 t, %1; cvt.u32.u64 %0, t; }" : "=r"(a) : "l"(p));
    return a;
}
__device__ __forceinline__ void ldsm_x4(unsigned* r, uint32_t addr) {
    asm volatile("ldmatrix.sync.aligned.m8n8.x4.shared.b16 {%0,%1,%2,%3}, [%4];"
                 : "=r"(r[0]), "=r"(r[1]), "=r"(r[2]), "=r"(r[3]) : "r"(addr));
}
__device__ __forceinline__ void mma_bf16(float* d, const unsigned* a, const unsigned* b) {
    asm volatile(
        "mma.sync.aligned.m16n8k16.row.col.f32.bf16.bf16.f32 "
        "{%0,%1,%2,%3}, {%4,%5,%6,%7}, {%8,%9}, {%0,%1,%2,%3};"
        : "+f"(d[0]), "+f"(d[1]), "+f"(d[2]), "+f"(d[3])
        : "r"(a[0]), "r"(a[1]), "r"(a[2]), "r"(a[3]), "r"(b[0]), "r"(b[1]));
}
__device__ __forceinline__ void mma_f16(float* d, const unsigned* a, const unsigned* b) {
    asm volatile(
        "mma.sync.aligned.m16n8k16.row.col.f32.f16.f16.f32 "
        "{%0,%1,%2,%3}, {%4,%5,%6,%7}, {%8,%9}, {%0,%1,%2,%3};"
        : "+f"(d[0]), "+f"(d[1]), "+f"(d[2]), "+f"(d[3])
        : "r"(a[0]), "r"(a[1]), "r"(a[2]), "r"(a[3]), "r"(b[0]), "r"(b[1]));
}
__device__ __forceinline__ void cp16(uint32_t dst, const void* src) {
    asm volatile("cp.async.ca.shared.global [%0], [%1], 16;" :: "r"(dst), "l"(src) : "memory");
}
#define CP_COMMIT() asm volatile("cp.async.commit_group;" ::: "memory")
#define CP_WAIT0()  asm volatile("cp.async.wait_group 0;" ::: "memory")

// ===========================================================================
// Scratch (device globals)
// ===========================================================================
__device__ __align__(16) __half g_WhT_hi[HH * DD * NN];  // [h][n=128][k=4096]
__device__ __align__(16) __half g_WhT_lo[HH * DD * NN];
__device__ __align__(16) __nv_bfloat16 g_Xhi[NN * 512];
__device__ __align__(16) __nv_bfloat16 g_Xlo[NN * 512];
__device__ __align__(16) __nv_bfloat16 g_Wt_hi[HH * DD * 512];
__device__ __align__(16) __nv_bfloat16 g_Wt_lo[HH * DD * 512];
__device__ float g_f1[HH * NN];
__device__ float g_f2[HH * NN];
__device__ float g_f2max[HH];
__device__ __align__(16) float g_colB[HH * NN];
__device__ __align__(16) float g_colD[HH * NN];
__device__ unsigned g_mask[NN * 128];

// ===========================================================================
// adj > 0 -> bitmask
// ===========================================================================
__global__ void build_mask_kernel(const float* __restrict__ adj,
                                  unsigned* __restrict__ mask) {
    int i = blockIdx.x;
    int t = threadIdx.x;
    int lane = t & 31;
    const float* row = adj + (size_t)i * NN;
    for (int word = t >> 5; word < 128; word += 8) {
        float v = row[word * 32 + lane];
        unsigned b = __ballot_sync(0xffffffffu, v > 0.f);
        if (lane == 0) mask[i * 128 + word] = b;
    }
}

__global__ void hrc_kernel(const int* __restrict__ head, const int* __restrict__ rel,
                           const float* __restrict__ ee, const float* __restrict__ re,
                           float* __restrict__ out) {
    int i = blockIdx.x;
    int d = threadIdx.x;
    out[(size_t)i * 128 + d] =
        ee[(size_t)head[i] * 128 + d] + re[(size_t)rel[i] * 128 + d];
}

// ===========================================================================
// fp32 -> bf16 hi/lo split (flat) — layer-0 input (ee) only
// ===========================================================================
__global__ void split_kernel(const float* __restrict__ src,
                             __nv_bfloat16* __restrict__ hi,
                             __nv_bfloat16* __restrict__ lo, int n) {
    int i = blockIdx.x * 256 + threadIdx.x;
    if (i < n) {
        float v = src[i];
        __nv_bfloat16 h = __float2bfloat16(v);
        hi[i] = h;
        lo[i] = __float2bfloat16(v - __bfloat162float(h));
    }
}

// ===========================================================================
// transpose + split bf16: weights [h][kdim][128] -> [h][128][kdim]
// ===========================================================================
__global__ void wt_split_kernel(const float* __restrict__ src,
                                __nv_bfloat16* __restrict__ dhi,
                                __nv_bfloat16* __restrict__ dlo, int kdim) {
    int h = blockIdx.z;
    int kbase = blockIdx.x * 32;
    int nbase = blockIdx.y * 32;
    __shared__ float ts[32][33];
    const float* sp = src + (size_t)h * kdim * 128;
    int t = threadIdx.x;
#pragma unroll
    for (int l = 0; l < 4; l++) {
        int e = t + l * 256;
        int r = e >> 5, c = e & 31;
        ts[r][c] = sp[(size_t)(kbase + r) * 128 + nbase + c];
    }
    __syncthreads();
#pragma unroll
    for (int l = 0; l < 4; l++) {
        int e = t + l * 256;
        int r = e >> 5, c = e & 31;
        float v = ts[c][r];
        __nv_bfloat16 hi = __float2bfloat16(v);
        __nv_bfloat16 lo = __float2bfloat16(v - __bfloat162float(hi));
        size_t o = (size_t)(h * 128 + nbase + r) * kdim + kbase + c;
        dhi[o] = hi;
        dlo[o] = lo;
    }
}

// ===========================================================================
// FUSED GEMM: Wh_tile = X @ W (3-pass bf16 split, fp32 acc), then in-epilogue:
//   f1/f2 row dots, transposed fp16 hi/lo WhT write. No fp32 Wh anywhere.
// CTA: 64m x 128n, grid (64, H). Dynamic smem:
//   [0, 30720): mainloop tiles Ahi/Alo/Bhi/Blo
//   after barrier, reuse: [0, 33280): Wstage float[64][130]; [33280,+1024): fred
// ===========================================================================
#define GEMM_SMEM 34560

__global__ void __launch_bounds__(256)
gemm_fused_kernel(const __nv_bfloat16* __restrict__ Xhi, const __nv_bfloat16* __restrict__ Xlo,
                  const __nv_bfloat16* __restrict__ WtHi, const __nv_bfloat16* __restrict__ WtLo,
                  const float* __restrict__ Avec,
                  __half* __restrict__ WhTh, __half* __restrict__ WhTl,
                  float* __restrict__ f1g, float* __restrict__ f2g, int Fin) {
    extern __shared__ __align__(16) char smem[];
    uint32_t sb = smem_u32(smem);
    const uint32_t sAhi = sb;
    const uint32_t sAlo = sb + 5120;
    const uint32_t sBhi = sb + 10240;
    const uint32_t sBlo = sb + 20480;

    int h = blockIdx.y;
    int row0 = blockIdx.x * 64;
    int t = threadIdx.x, wid = t >> 5, lane = t & 31;
    int wr = wid & 3, wc = wid >> 2;
    const __nv_bfloat16* Wth = WtHi + (size_t)h * 128 * Fin;
    const __nv_bfloat16* Wtl = WtLo + (size_t)h * 128 * Fin;

    float d[8][4] = {};

    uint32_t a_off = (uint32_t)(wr * 16 + ((lane >> 3) & 1) * 8 + (lane & 7)) * (PSTR * 2)
                   + (uint32_t)((lane >> 4) * 8) * 2;
    uint32_t b_roff = (uint32_t)(wc * 64 + (lane >> 4) * 8 + (lane & 7)) * (PSTR * 2);
    uint32_t b_koff = (uint32_t)(((lane >> 3) & 1) * 8) * 2;

    for (int k0 = 0; k0 < Fin; k0 += 32) {
        __syncthreads();
        {
            int m = t >> 2, q = t & 3;
            size_t go = (size_t)(row0 + m) * Fin + k0 + q * 8;
            *(uint4*)(smem + 0    + m * 80 + q * 16) = *(const uint4*)(Xhi + go);
            *(uint4*)(smem + 5120 + m * 80 + q * 16) = *(const uint4*)(Xlo + go);
        }
#pragma unroll
        for (int l = 0; l < 2; l++) {
            int idx = t + l * 256;
            int n = idx >> 2, q = idx & 3;
            size_t go = (size_t)n * Fin + k0 + q * 8;
            *(uint4*)(smem + 10240 + n * 80 + q * 16) = *(const uint4*)(Wth + go);
            *(uint4*)(smem + 20480 + n * 80 + q * 16) = *(const uint4*)(Wtl + go);
        }
        __syncthreads();
#pragma unroll
        for (int s = 0; s < 2; s++) {
            unsigned ah[4], al[4];
            ldsm_x4(ah, sAhi + a_off + s * 32);
            ldsm_x4(al, sAlo + a_off + s * 32);
#pragma unroll
            for (int pp = 0; pp < 4; pp++) {
                unsigned bh[4], bl[4];
                uint32_t boff = b_roff + (uint32_t)(pp * 16) * (PSTR * 2) + b_koff + s * 32;
                ldsm_x4(bh, sBhi + boff);
                ldsm_x4(bl, sBlo + boff);
                mma_bf16(d[2 * pp],     ah, bh);
                mma_bf16(d[2 * pp + 1], ah, bh + 2);
                mma_bf16(d[2 * pp],     ah, bl);
                mma_bf16(d[2 * pp + 1], ah, bl + 2);
                mma_bf16(d[2 * pp],     al, bh);
                mma_bf16(d[2 * pp + 1], al, bh + 2);
            }
        }
    }

    // ------- fused epilogue -------
    __syncthreads();   // all ldsm reads done; smem is re-purposed below
    float* Ws = (float*)smem;              // [64][130]
    float* fr = (float*)(smem + 33280);    // [2 (f1/f2)][2 (wc)][64]
    const float* av = Avec + h * 256;

    int rloc = wr * 16 + (lane >> 2);
    int cb = wc * 64 + (lane & 3) * 2;
    float s1a = 0.f, s2a = 0.f, s1b = 0.f, s2b = 0.f;
#pragma unroll
    for (int nt = 0; nt < 8; nt++) {
        int col = cb + nt * 8;
        float a1x = av[col], a1y = av[col + 1];
        float a2x = av[128 + col], a2y = av[128 + col + 1];
        float d0 = d[nt][0], d1 = d[nt][1], d2 = d[nt][2], d3 = d[nt][3];
        Ws[rloc * 130 + col] = d0;
        Ws[rloc * 130 + col + 1] = d1;
        Ws[(rloc + 8) * 130 + col] = d2;
        Ws[(rloc + 8) * 130 + col + 1] = d3;
        s1a += d0 * a1x + d1 * a1y;
        s2a += d0 * a2x + d1 * a2y;
        s1b += d2 * a1x + d3 * a1y;
        s2b += d2 * a2x + d3 * a2y;
    }
    // reduce across the 4-lane row group (lanes 4q..4q+3)
#pragma unroll
    for (int o = 1; o <= 2; o <<= 1) {
        s1a += __shfl_xor_sync(0xffffffffu, s1a, o);
        s2a += __shfl_xor_sync(0xffffffffu, s2a, o);
        s1b += __shfl_xor_sync(0xffffffffu, s1b, o);
        s2b += __shfl_xor_sync(0xffffffffu, s2b, o);
    }
    if ((lane & 3) == 0) {
        fr[(0 * 2 + wc) * 64 + rloc] = s1a;
        fr[(0 * 2 + wc) * 64 + rloc + 8] = s1b;
        fr[(1 * 2 + wc) * 64 + rloc] = s2a;
        fr[(1 * 2 + wc) * 64 + rloc + 8] = s2b;
    }
    __syncthreads();
    if (t < 64) {
        f1g[h * NN + row0 + t] = fr[0 * 64 + t] + fr[1 * 64 + t];
        f2g[h * NN + row0 + t] = fr[2 * 64 + t] + fr[3 * 64 + t];
    }

    // transposed fp16 hi/lo write: task = (n, kg); thread t covers n = t/2,
    // kg = 4*(t&1)+i  (each task = 8 consecutive k = 16B per hi/lo)
#pragma unroll
    for (int i = 0; i < 4; i++) {
        int n = t >> 1, kg = 4 * (t & 1) + i;
        __half hv[8], lv[8];
#pragma unroll
        for (int j = 0; j < 8; j++) {
            float v = Ws[(kg * 8 + j) * 130 + n];
            __half hh = __float2half_rn(v);
            hv[j] = hh;
            lv[j] = __float2half_rn(v - __half2float(hh));
        }
        size_t o = (size_t)(h * 128 + n) * NN + row0 + kg * 8;
        *(uint4*)&WhTh[o] = *(uint4*)hv;
        *(uint4*)&WhTl[o] = *(uint4*)lv;
    }
}

// ===========================================================================
// merged: colB = exp(f2), colD = exp(0.2 f2), fmax[h] = max f2  (grid = H)
// ===========================================================================
__global__ void maxprep_kernel(const float* __restrict__ f2,
                               float* __restrict__ colB, float* __restrict__ colD,
                               float* __restrict__ fmax) {
    int h = blockIdx.x;
    __shared__ float red[32];
    float m = -1e30f;
#pragma unroll
    for (int l = 0; l < 4; l++) {
        int i = threadIdx.x + l * 1024;
        int idx = h * NN + i;
        float b = f2[idx];
        colB[idx] = __expf(b);
        colD[idx] = __expf(0.2f * b);
        m = fmaxf(m, b);
    }
#pragma unroll
    for (int o = 16; o; o >>= 1) m = fmaxf(m, __shfl_xor_sync(0xffffffffu, m, o));
    if ((threadIdx.x & 31) == 0) red[threadIdx.x >> 5] = m;
    __syncthreads();
    if (threadIdx.x < 32) {
        m = red[threadIdx.x];
#pragma unroll
        for (int o = 16; o; o >>= 1) m = fmaxf(m, __shfl_xor_sync(0xffffffffu, m, o));
        if (threadIdx.x == 0) fmax[h] = m;
    }
}

// ===========================================================================
// Pipelined mma.sync attention, 2-pass fp16 (unchanged from R10).
// ===========================================================================
#define ATT_SMEM 51456

__global__ void __launch_bounds__(256)
attn_mma_kernel(const __half* __restrict__ WhT_hi, const __half* __restrict__ WhT_lo,
                const float* __restrict__ f1v, const float* __restrict__ f2max,
                const float* __restrict__ colB, const float* __restrict__ colD,
                const unsigned* __restrict__ mask,
                float* __restrict__ out, int out_stride,
                __nv_bfloat16* __restrict__ xhi, __nv_bfloat16* __restrict__ xlo) {
    extern __shared__ __align__(16) char smem[];
    uint32_t sb = smem_u32(smem);
    const uint32_t sP = sb;
    const uint32_t sB = sb + 10240;
    float* rsum = (float*)(smem + 51200);

    int h = blockIdx.y;
    int row0 = blockIdx.x * 64;
    int hbase = h * NN;
    int t = threadIdx.x, wid = t >> 5, lane = t & 31;
    int wr = wid & 3, wc = wid >> 2;

    const __half* Whh = WhT_hi + (size_t)(h * 128) * NN;
    const __half* Whl = WhT_lo + (size_t)(h * 128) * NN;

    int pr = t >> 2, kq = t & 3;
    float f1r = f1v[hbase + row0 + pr];
    float mF2 = f2max[h];
    float xm = f1r + mF2;
    float m = xm > 0.f ? xm : 0.2f * xm;
    float Ar = __expf(f1r - m);
    float Cr = __expf(0.2f * f1r - m);
    float psum = 0.f;

    const unsigned* mrow = mask + (size_t)(row0 + pr) * 128;
    const float* cBp = colB + hbase;
    const float* cDp = colD + hbase;

    uint32_t a_off = (uint32_t)(wr * 16 + ((lane >> 3) & 1) * 8 + (lane & 7)) * (PSTR * 2)
                   + (uint32_t)((lane >> 4) * 8) * 2;
    uint32_t b_roff = (uint32_t)(wc * 64 + (lane >> 4) * 8 + (lane & 7)) * (PSTR * 2);
    uint32_t b_koff = (uint32_t)(((lane >> 3) & 1) * 8) * 2;

    float d[8][4] = {};

    auto stage = [&](int c, int buf) {
#pragma unroll
        for (int l = 0; l < 2; l++) {
            int idx = t + l * 256;
            int n = idx >> 2, q = idx & 3;
            size_t go = (size_t)n * NN + c * 32 + q * 8;
            cp16(sB + (uint32_t)(buf * 2 + 0) * 10240 + n * 80 + q * 16, Whh + go);
            cp16(sB + (uint32_t)(buf * 2 + 1) * 10240 + n * 80 + q * 16, Whl + go);
        }
        CP_COMMIT();
    };
    auto pgen = [&](int c, int buf) {
        int kb = c * 32 + kq * 8;
        unsigned w8 = mrow[c] >> (kq * 8);
        float4 b0 = *(const float4*)(cBp + kb);
        float4 b1 = *(const float4*)(cBp + kb + 4);
        float4 d0 = *(const float4*)(cDp + kb);
        float4 d1 = *(const float4*)(cDp + kb + 4);
        float p[8];
        p[0] = (w8 & 1u)   ? fmaxf(Ar * b0.x, Cr * d0.x) : 0.f;
        p[1] = (w8 & 2u)   ? fmaxf(Ar * b0.y, Cr * d0.y) : 0.f;
        p[2] = (w8 & 4u)   ? fmaxf(Ar * b0.z, Cr * d0.z) : 0.f;
        p[3] = (w8 & 8u)   ? fmaxf(Ar * b0.w, Cr * d0.w) : 0.f;
        p[4] = (w8 & 16u)  ? fmaxf(Ar * b1.x, Cr * d1.x) : 0.f;
        p[5] = (w8 & 32u)  ? fmaxf(Ar * b1.y, Cr * d1.y) : 0.f;
        p[6] = (w8 & 64u)  ? fmaxf(Ar * b1.z, Cr * d1.z) : 0.f;
        p[7] = (w8 & 128u) ? fmaxf(Ar * b1.w, Cr * d1.w) : 0.f;
        psum += ((p[0] + p[1]) + (p[2] + p[3])) + ((p[4] + p[5]) + (p[6] + p[7]));
        uint4 u;
        unsigned* ph = &u.x;
#pragma unroll
        for (int j = 0; j < 4; j++) {
            __half2 h2 = __floats2half2_rn(p[2 * j], p[2 * j + 1]);
            ph[j] = *(unsigned*)&h2;
        }
        *(uint4*)(smem + buf * 5120 + pr * 80 + kq * 16) = u;
    };

    stage(0, 0);
    pgen(0, 0);

    for (int c = 0; c < 128; c++) {
        int buf = c & 1;
        CP_WAIT0();
        __syncthreads();
        if (c + 1 < 128) {
            stage(c + 1, buf ^ 1);
            pgen(c + 1, buf ^ 1);
        }
        uint32_t pH = sP + (uint32_t)buf * 5120;
        uint32_t bH = sB + (uint32_t)(buf * 2 + 0) * 10240;
        uint32_t bL = sB + (uint32_t)(buf * 2 + 1) * 10240;
#pragma unroll
        for (int s = 0; s < 2; s++) {
            unsigned ah[4];
            ldsm_x4(ah, pH + a_off + s * 32);
#pragma unroll
            for (int pp = 0; pp < 4; pp++) {
                unsigned bh[4], bl[4];
                uint32_t boff = b_roff + (uint32_t)(pp * 16) * (PSTR * 2) + b_koff + s * 32;
                ldsm_x4(bh, bH + boff);
                ldsm_x4(bl, bL + boff);
                mma_f16(d[2 * pp],     ah, bh);
                mma_f16(d[2 * pp + 1], ah, bh + 2);
                mma_f16(d[2 * pp],     ah, bl);
                mma_f16(d[2 * pp + 1], ah, bl + 2);
            }
        }
    }

    psum += __shfl_xor_sync(0xffffffffu, psum, 1);
    psum += __shfl_xor_sync(0xffffffffu, psum, 2);
    if (kq == 0) rsum[pr] = psum;
    __syncthreads();

    int rloc = wr * 16 + (lane >> 2);
    float inv0 = 1.f / rsum[rloc];
    float inv1 = 1.f / rsum[rloc + 8];
    int r0 = row0 + rloc;
    int cbase = h * 128 + wc * 64 + (lane & 3) * 2;
#pragma unroll
    for (int nt = 0; nt < 8; nt++) {
        int col = cbase + nt * 8;
        float v0 = d[nt][0] * inv0, v1 = d[nt][1] * inv0;
        float v2 = d[nt][2] * inv1, v3 = d[nt][3] * inv1;
        v0 = v0 > 0.f ? v0 : expm1f(v0);
        v1 = v1 > 0.f ? v1 : expm1f(v1);
        v2 = v2 > 0.f ? v2 : expm1f(v2);
        v3 = v3 > 0.f ? v3 : expm1f(v3);
        if (xhi) {
            __nv_bfloat16 h0 = __float2bfloat16(v0), h1 = __float2bfloat16(v1);
            __nv_bfloat16 h2 = __float2bfloat16(v2), h3 = __float2bfloat16(v3);
            __nv_bfloat16 l0 = __float2bfloat16(v0 - __bfloat162float(h0));
            __nv_bfloat16 l1 = __float2bfloat16(v1 - __bfloat162float(h1));
            __nv_bfloat16 l2 = __float2bfloat16(v2 - __bfloat162float(h2));
            __nv_bfloat16 l3 = __float2bfloat16(v3 - __bfloat162float(h3));
            *(__nv_bfloat162*)&xhi[(size_t)r0 * 512 + col] = __nv_bfloat162(h0, h1);
            *(__nv_bfloat162*)&xlo[(size_t)r0 * 512 + col] = __nv_bfloat162(l0, l1);
            *(__nv_bfloat162*)&xhi[(size_t)(r0 + 8) * 512 + col] = __nv_bfloat162(h2, h3);
            *(__nv_bfloat162*)&xlo[(size_t)(r0 + 8) * 512 + col] = __nv_bfloat162(l2, l3);
        } else {
            *(float2*)&out[(size_t)r0 * out_stride + col] = make_float2(v0, v1);
            *(float2*)&out[(size_t)(r0 + 8) * out_stride + col] = make_float2(v2, v3);
        }
    }
}

// ===========================================================================
extern "C" void kernel_launch(void* const* d_in, const int* in_sizes, int n_in,
                              void* d_out, int out_size) {
    const int* head = (const int*)d_in[0];
    const int* rel = (const int*)d_in[1];
    const float* adj = (const float*)d_in[2];
    const float* ee = (const float*)d_in[3];
    const float* re = (const float*)d_in[4];
    const float* W0 = (const float*)d_in[5];
    const float* a0 = (const float*)d_in[6];
    const float* Wm = (const float*)d_in[7];
    const float* am = (const float*)d_in[8];
    const float* Wo = (const float*)d_in[9];
    const float* ao = (const float*)d_in[10];
    float* out = (float*)d_out;

    float *f1, *f2, *fmax, *cB, *cD;
    __half *WhTh, *WhTl;
    __nv_bfloat16 *Xhi, *Xlo, *Wth, *Wtl;
    unsigned* mask;
    cudaGetSymbolAddress((void**)&f1, g_f1);
    cudaGetSymbolAddress((void**)&f2, g_f2);
    cudaGetSymbolAddress((void**)&fmax, g_f2max);
    cudaGetSymbolAddress((void**)&cB, g_colB);
    cudaGetSymbolAddress((void**)&cD, g_colD);
    cudaGetSymbolAddress((void**)&WhTh, g_WhT_hi);
    cudaGetSymbolAddress((void**)&WhTl, g_WhT_lo);
    cudaGetSymbolAddress((void**)&Xhi, g_Xhi);
    cudaGetSymbolAddress((void**)&Xlo, g_Xlo);
    cudaGetSymbolAddress((void**)&Wth, g_Wt_hi);
    cudaGetSymbolAddress((void**)&Wtl, g_Wt_lo);
    cudaGetSymbolAddress((void**)&mask, g_mask);

    cudaFuncSetAttribute(attn_mma_kernel, cudaFuncAttributeMaxDynamicSharedMemorySize, ATT_SMEM);
    cudaFuncSetAttribute(gemm_fused_kernel, cudaFuncAttributeMaxDynamicSharedMemorySize, GEMM_SMEM);

    build_mask_kernel<<<NN, 256>>>(adj, mask);
    hrc_kernel<<<NN, 128>>>(head, rel, ee, re, out + (size_t)NN * 128);

    // ---- layer 0: Fin = 128, X = entity_emb ----
    split_kernel<<<(NN * 128 + 255) / 256, 256>>>(ee, Xhi, Xlo, NN * 128);
    wt_split_kernel<<<dim3(4, 4, HH), 256>>>(W0, Wth, Wtl, 128);
    gemm_fused_kernel<<<dim3(64, HH), 256, GEMM_SMEM>>>(Xhi, Xlo, Wth, Wtl, a0,
                                                        WhTh, WhTl, f1, f2, 128);
    maxprep_kernel<<<HH, 1024>>>(f2, cB, cD, fmax);
    attn_mma_kernel<<<dim3(64, HH), 256, ATT_SMEM>>>(WhTh, WhTl, f1, fmax, cB, cD, mask,
                                                     nullptr, 0, Xhi, Xlo);

    // ---- 9 middle layers: Fin = 512 ----
    for (int l = 0; l < NMID; l++) {
        wt_split_kernel<<<dim3(16, 4, HH), 256>>>(Wm + (size_t)l * HH * 512 * 128, Wth, Wtl, 512);
        gemm_fused_kernel<<<dim3(64, HH), 256, GEMM_SMEM>>>(Xhi, Xlo, Wth, Wtl,
                                                            am + (size_t)l * HH * 256,
                                                            WhTh, WhTl, f1, f2, 512);
        maxprep_kernel<<<HH, 1024>>>(f2, cB, cD, fmax);
        attn_mma_kernel<<<dim3(64, HH), 256, ATT_SMEM>>>(WhTh, WhTl, f1, fmax, cB, cD, mask,
                                                         nullptr, 0, Xhi, Xlo);
    }

    // ---- output layer: 1 head, Fin = 512 ----
    wt_split_kernel<<<dim3(16, 4, 1), 256>>>(Wo, Wth, Wtl, 512);
    gemm_fused_kernel<<<dim3(64, 1), 256, GEMM_SMEM>>>(Xhi, Xlo, Wth, Wtl, ao,
                                                       WhTh, WhTl, f1, f2, 512);
    maxprep_kernel<<<1, 1024>>>(f2, cB, cD, fmax);
    attn_mma_kernel<<<dim3(64, 1), 256, ATT_SMEM>>>(WhTh, WhTl, f1, fmax, cB, cD, mask,
                                                    out, 128, nullptr, nullptr);
}

// round 12
// speedup vs baseline: 2.1158x; 1.3249x over previous
#include <cuda_runtime.h>
#include <cuda_bf16.h>
#include <cuda_fp16.h>
#include <math.h>
#include <cstdint>

#define NN 4096
#define DD 128
#define HH 4
#define NMID 9
#define PSTR 40  // 16-bit elems per smem row (80B, ldmatrix conflict-free)

typedef unsigned long long u64;

// Wt (split weights) layout offsets, in elements
#define WT_OFF0 0
#define WT_OFFM(l) (65536 + (size_t)(l) * 262144)
#define WT_OFFO 2424832
#define WT_TOTAL 2490368

// ===========================================================================
// PTX helpers (sm_80-class: compiles for plain sm_103)
// ===========================================================================
__device__ __forceinline__ uint32_t smem_u32(const void* p) {
    uint32_t a;
    asm("{ .reg .u64 t; cvta.to.shared.u64 t, %1; cvt.u32.u64 %0, t; }" : "=r"(a) : "l"(p));
    return a;
}
__device__ __forceinline__ void ldsm_x4(unsigned* r, uint32_t addr) {
    asm volatile("ldmatrix.sync.aligned.m8n8.x4.shared.b16 {%0,%1,%2,%3}, [%4];"
                 : "=r"(r[0]), "=r"(r[1]), "=r"(r[2]), "=r"(r[3]) : "r"(addr));
}
__device__ __forceinline__ void mma_bf16(float* d, const unsigned* a, const unsigned* b) {
    asm volatile(
        "mma.sync.aligned.m16n8k16.row.col.f32.bf16.bf16.f32 "
        "{%0,%1,%2,%3}, {%4,%5,%6,%7}, {%8,%9}, {%0,%1,%2,%3};"
        : "+f"(d[0]), "+f"(d[1]), "+f"(d[2]), "+f"(d[3])
        : "r"(a[0]), "r"(a[1]), "r"(a[2]), "r"(a[3]), "r"(b[0]), "r"(b[1]));
}
__device__ __forceinline__ void mma_f16(float* d, const unsigned* a, const unsigned* b) {
    asm volatile(
        "mma.sync.aligned.m16n8k16.row.col.f32.f16.f16.f32 "
        "{%0,%1,%2,%3}, {%4,%5,%6,%7}, {%8,%9}, {%0,%1,%2,%3};"
        : "+f"(d[0]), "+f"(d[1]), "+f"(d[2]), "+f"(d[3])
        : "r"(a[0]), "r"(a[1]), "r"(a[2]), "r"(a[3]), "r"(b[0]), "r"(b[1]));
}
__device__ __forceinline__ void cp16(uint32_t dst, const void* src) {
    asm volatile("cp.async.ca.shared.global [%0], [%1], 16;" :: "r"(dst), "l"(src) : "memory");
}
#define CP_COMMIT() asm volatile("cp.async.commit_group;" ::: "memory")
#define CP_WAIT0()  asm volatile("cp.async.wait_group 0;" ::: "memory")

// ===========================================================================
// Scratch (device globals)
// ===========================================================================
__device__ __align__(16) __half g_WhT[HH * DD * NN];   // [h][n=128][k=4096] fp16
__device__ __align__(16) __nv_bfloat16 g_Xhi[NN * 512];
__device__ __align__(16) __nv_bfloat16 g_Xlo[NN * 512];
__device__ __align__(16) __nv_bfloat16 g_Wt_hi[WT_TOTAL];  // all layers' split weights
__device__ __align__(16) __nv_bfloat16 g_Wt_lo[WT_TOTAL];
__device__ float g_f1[HH * NN];
__device__ float g_f2[HH * NN];
__device__ float g_f2max[HH];
__device__ __align__(16) float g_colB[HH * NN];
__device__ __align__(16) float g_colD[HH * NN];
__device__ unsigned g_mask[NN * 128];

// ===========================================================================
// adj > 0 -> bitmask
// ===========================================================================
__global__ void build_mask_kernel(const float* __restrict__ adj,
                                  unsigned* __restrict__ mask) {
    int i = blockIdx.x;
    int t = threadIdx.x;
    int lane = t & 31;
    const float* row = adj + (size_t)i * NN;
    for (int word = t >> 5; word < 128; word += 8) {
        float v = row[word * 32 + lane];
        unsigned b = __ballot_sync(0xffffffffu, v > 0.f);
        if (lane == 0) mask[i * 128 + word] = b;
    }
}

__global__ void hrc_kernel(const int* __restrict__ head, const int* __restrict__ rel,
                           const float* __restrict__ ee, const float* __restrict__ re,
                           float* __restrict__ out) {
    int i = blockIdx.x;
    int d = threadIdx.x;
    out[(size_t)i * 128 + d] =
        ee[(size_t)head[i] * 128 + d] + re[(size_t)rel[i] * 128 + d];
}

// ===========================================================================
// fp32 -> bf16 hi/lo split (flat) — layer-0 input (ee) only
// ===========================================================================
__global__ void split_kernel(const float* __restrict__ src,
                             __nv_bfloat16* __restrict__ hi,
                             __nv_bfloat16* __restrict__ lo, int n) {
    int i = blockIdx.x * 256 + threadIdx.x;
    if (i < n) {
        float v = src[i];
        __nv_bfloat16 h = __float2bfloat16(v);
        hi[i] = h;
        lo[i] = __float2bfloat16(v - __bfloat162float(h));
    }
}

// ===========================================================================
// ONE-SHOT weight transpose + bf16 split for ALL 11 layers.
// grid = 2432 tile-blocks of 32k x 32n. Decode: [0,64)=W0, [64,2368)=Wm, rest=Wo.
// ===========================================================================
__global__ void wsplit_all_kernel(const float* __restrict__ W0,
                                  const float* __restrict__ Wm,
                                  const float* __restrict__ Wo,
                                  __nv_bfloat16* __restrict__ dhi,
                                  __nv_bfloat16* __restrict__ dlo) {
    int b = blockIdx.x;
    const float* src;
    int kdim, kt, nt;
    size_t dst;
    if (b < 64) {
        int h = b >> 4, rem = b & 15;
        kt = rem >> 2; nt = rem & 3;
        src = W0 + (size_t)h * 128 * 128;
        kdim = 128;
        dst = WT_OFF0 + (size_t)h * 128 * 128;
    } else if (b < 2368) {
        int b2 = b - 64;
        int l = b2 >> 8, rem = b2 & 255;
        int h = rem >> 6, rem2 = rem & 63;
        kt = rem2 >> 2; nt = rem2 & 3;
        src = Wm + ((size_t)l * HH + h) * 512 * 128;
        kdim = 512;
        dst = WT_OFFM(l) + (size_t)h * 512 * 128;
    } else {
        int rem = b - 2368;
        kt = rem >> 2; nt = rem & 3;
        src = Wo;
        kdim = 512;
        dst = WT_OFFO;
    }
    int kbase = kt * 32, nbase = nt * 32;
    __shared__ float ts[32][33];
    int t = threadIdx.x;
#pragma unroll
    for (int l = 0; l < 4; l++) {
        int e = t + l * 256;
        int r = e >> 5, c = e & 31;
        ts[r][c] = src[(size_t)(kbase + r) * 128 + nbase + c];
    }
    __syncthreads();
#pragma unroll
    for (int l = 0; l < 4; l++) {
        int e = t + l * 256;
        int r = e >> 5, c = e & 31;  // r = n-local, c = k-local
        float v = ts[c][r];
        __nv_bfloat16 hi = __float2bfloat16(v);
        __nv_bfloat16 lo = __float2bfloat16(v - __bfloat162float(hi));
        size_t o = dst + (size_t)(nbase + r) * kdim + kbase + c;
        dhi[o] = hi;
        dlo[o] = lo;
    }
}

// ===========================================================================
// FUSED GEMM: Wh_tile = X @ W (3-pass bf16 split, fp32 acc); epilogue computes
// f1/f2 row dots and writes transposed fp16 WhT (single precision copy).
// CTA: 64m x 128n, grid (64, H). Dynamic smem:
//   [0, 30720): mainloop tiles; reuse after barrier:
//   [0, 33280): Wstage float[64][130]; [33280,+1024): fred
// ===========================================================================
#define GEMM_SMEM 34560

__global__ void __launch_bounds__(256)
gemm_fused_kernel(const __nv_bfloat16* __restrict__ Xhi, const __nv_bfloat16* __restrict__ Xlo,
                  const __nv_bfloat16* __restrict__ WtHi, const __nv_bfloat16* __restrict__ WtLo,
                  const float* __restrict__ Avec,
                  __half* __restrict__ WhT,
                  float* __restrict__ f1g, float* __restrict__ f2g, int Fin) {
    extern __shared__ __align__(16) char smem[];
    uint32_t sb = smem_u32(smem);
    const uint32_t sAhi = sb;
    const uint32_t sAlo = sb + 5120;
    const uint32_t sBhi = sb + 10240;
    const uint32_t sBlo = sb + 20480;

    int h = blockIdx.y;
    int row0 = blockIdx.x * 64;
    int t = threadIdx.x, wid = t >> 5, lane = t & 31;
    int wr = wid & 3, wc = wid >> 2;
    const __nv_bfloat16* Wth = WtHi + (size_t)h * 128 * Fin;
    const __nv_bfloat16* Wtl = WtLo + (size_t)h * 128 * Fin;

    float d[8][4] = {};

    uint32_t a_off = (uint32_t)(wr * 16 + ((lane >> 3) & 1) * 8 + (lane & 7)) * (PSTR * 2)
                   + (uint32_t)((lane >> 4) * 8) * 2;
    uint32_t b_roff = (uint32_t)(wc * 64 + (lane >> 4) * 8 + (lane & 7)) * (PSTR * 2);
    uint32_t b_koff = (uint32_t)(((lane >> 3) & 1) * 8) * 2;

    for (int k0 = 0; k0 < Fin; k0 += 32) {
        __syncthreads();
        {
            int m = t >> 2, q = t & 3;
            size_t go = (size_t)(row0 + m) * Fin + k0 + q * 8;
            *(uint4*)(smem + 0    + m * 80 + q * 16) = *(const uint4*)(Xhi + go);
            *(uint4*)(smem + 5120 + m * 80 + q * 16) = *(const uint4*)(Xlo + go);
        }
#pragma unroll
        for (int l = 0; l < 2; l++) {
            int idx = t + l * 256;
            int n = idx >> 2, q = idx & 3;
            size_t go = (size_t)n * Fin + k0 + q * 8;
            *(uint4*)(smem + 10240 + n * 80 + q * 16) = *(const uint4*)(Wth + go);
            *(uint4*)(smem + 20480 + n * 80 + q * 16) = *(const uint4*)(Wtl + go);
        }
        __syncthreads();
#pragma unroll
        for (int s = 0; s < 2; s++) {
            unsigned ah[4], al[4];
            ldsm_x4(ah, sAhi + a_off + s * 32);
            ldsm_x4(al, sAlo + a_off + s * 32);
#pragma unroll
            for (int pp = 0; pp < 4; pp++) {
                unsigned bh[4], bl[4];
                uint32_t boff = b_roff + (uint32_t)(pp * 16) * (PSTR * 2) + b_koff + s * 32;
                ldsm_x4(bh, sBhi + boff);
                ldsm_x4(bl, sBlo + boff);
                mma_bf16(d[2 * pp],     ah, bh);
                mma_bf16(d[2 * pp + 1], ah, bh + 2);
                mma_bf16(d[2 * pp],     ah, bl);
                mma_bf16(d[2 * pp + 1], ah, bl + 2);
                mma_bf16(d[2 * pp],     al, bh);
                mma_bf16(d[2 * pp + 1], al, bh + 2);
            }
        }
    }

    // ------- fused epilogue -------
    __syncthreads();   // all ldsm reads done; smem re-purposed
    float* Ws = (float*)smem;              // [64][130]
    float* fr = (float*)(smem + 33280);    // [2 (f1/f2)][2 (wc)][64]
    const float* av = Avec + h * 256;

    int rloc = wr * 16 + (lane >> 2);
    int cb = wc * 64 + (lane & 3) * 2;
    float s1a = 0.f, s2a = 0.f, s1b = 0.f, s2b = 0.f;
#pragma unroll
    for (int nt = 0; nt < 8; nt++) {
        int col = cb + nt * 8;
        float a1x = av[col], a1y = av[col + 1];
        float a2x = av[128 + col], a2y = av[128 + col + 1];
        float d0 = d[nt][0], d1 = d[nt][1], d2 = d[nt][2], d3 = d[nt][3];
        Ws[rloc * 130 + col] = d0;
        Ws[rloc * 130 + col + 1] = d1;
        Ws[(rloc + 8) * 130 + col] = d2;
        Ws[(rloc + 8) * 130 + col + 1] = d3;
        s1a += d0 * a1x + d1 * a1y;
        s2a += d0 * a2x + d1 * a2y;
        s1b += d2 * a1x + d3 * a1y;
        s2b += d2 * a2x + d3 * a2y;
    }
#pragma unroll
    for (int o = 1; o <= 2; o <<= 1) {
        s1a += __shfl_xor_sync(0xffffffffu, s1a, o);
        s2a += __shfl_xor_sync(0xffffffffu, s2a, o);
        s1b += __shfl_xor_sync(0xffffffffu, s1b, o);
        s2b += __shfl_xor_sync(0xffffffffu, s2b, o);
    }
    if ((lane & 3) == 0) {
        fr[(0 * 2 + wc) * 64 + rloc] = s1a;
        fr[(0 * 2 + wc) * 64 + rloc + 8] = s1b;
        fr[(1 * 2 + wc) * 64 + rloc] = s2a;
        fr[(1 * 2 + wc) * 64 + rloc + 8] = s2b;
    }
    __syncthreads();
    if (t < 64) {
        f1g[h * NN + row0 + t] = fr[0 * 64 + t] + fr[1 * 64 + t];
        f2g[h * NN + row0 + t] = fr[2 * 64 + t] + fr[3 * 64 + t];
    }

    // transposed fp16 write: thread t covers n = t/2, kg = 4*(t&1)+i
#pragma unroll
    for (int i = 0; i < 4; i++) {
        int n = t >> 1, kg = 4 * (t & 1) + i;
        __half hv[8];
#pragma unroll
        for (int j = 0; j < 8; j++)
            hv[j] = __float2half_rn(Ws[(kg * 8 + j) * 130 + n]);
        size_t o = (size_t)(h * 128 + n) * NN + row0 + kg * 8;
        *(uint4*)&WhT[o] = *(uint4*)hv;
    }
}

// ===========================================================================
// merged: colB = exp(f2), colD = exp(0.2 f2), fmax[h] = max f2  (grid = H)
// ===========================================================================
__global__ void maxprep_kernel(const float* __restrict__ f2,
                               float* __restrict__ colB, float* __restrict__ colD,
                               float* __restrict__ fmax) {
    int h = blockIdx.x;
    __shared__ float red[32];
    float m = -1e30f;
#pragma unroll
    for (int l = 0; l < 4; l++) {
        int i = threadIdx.x + l * 1024;
        int idx = h * NN + i;
        float b = f2[idx];
        colB[idx] = __expf(b);
        colD[idx] = __expf(0.2f * b);
        m = fmaxf(m, b);
    }
#pragma unroll
    for (int o = 16; o; o >>= 1) m = fmaxf(m, __shfl_xor_sync(0xffffffffu, m, o));
    if ((threadIdx.x & 31) == 0) red[threadIdx.x >> 5] = m;
    __syncthreads();
    if (threadIdx.x < 32) {
        m = red[threadIdx.x];
#pragma unroll
        for (int o = 16; o; o >>= 1) m = fmaxf(m, __shfl_xor_sync(0xffffffffu, m, o));
        if (threadIdx.x == 0) fmax[h] = m;
    }
}

// ===========================================================================
// Pipelined mma.sync attention, SINGLE-pass fp16 (P fp16, WhT fp16).
// CTA 64m x 128n, grid (64, H). smem:
//   P[buf]: buf*5120              (64 rows x 80B)   total 10240
//   B[buf]: 10240 + buf*10240     (128 rows x 80B)  total 20480
//   rowsum: 30720 (64 floats)
// ===========================================================================
#define ATT_SMEM 30976

__global__ void __launch_bounds__(256)
attn_mma_kernel(const __half* __restrict__ WhT,
                const float* __restrict__ f1v, const float* __restrict__ f2max,
                const float* __restrict__ colB, const float* __restrict__ colD,
                const unsigned* __restrict__ mask,
                float* __restrict__ out, int out_stride,
                __nv_bfloat16* __restrict__ xhi, __nv_bfloat16* __restrict__ xlo) {
    extern __shared__ __align__(16) char smem[];
    uint32_t sb = smem_u32(smem);
    const uint32_t sP = sb;
    const uint32_t sB = sb + 10240;
    float* rsum = (float*)(smem + 30720);

    int h = blockIdx.y;
    int row0 = blockIdx.x * 64;
    int hbase = h * NN;
    int t = threadIdx.x, wid = t >> 5, lane = t & 31;
    int wr = wid & 3, wc = wid >> 2;

    const __half* Whh = WhT + (size_t)(h * 128) * NN;

    int pr = t >> 2, kq = t & 3;
    float f1r = f1v[hbase + row0 + pr];
    float mF2 = f2max[h];
    float xm = f1r + mF2;
    float m = xm > 0.f ? xm : 0.2f * xm;
    float Ar = __expf(f1r - m);
    float Cr = __expf(0.2f * f1r - m);
    float psum = 0.f;

    const unsigned* mrow = mask + (size_t)(row0 + pr) * 128;
    const float* cBp = colB + hbase;
    const float* cDp = colD + hbase;

    uint32_t a_off = (uint32_t)(wr * 16 + ((lane >> 3) & 1) * 8 + (lane & 7)) * (PSTR * 2)
                   + (uint32_t)((lane >> 4) * 8) * 2;
    uint32_t b_roff = (uint32_t)(wc * 64 + (lane >> 4) * 8 + (lane & 7)) * (PSTR * 2);
    uint32_t b_koff = (uint32_t)(((lane >> 3) & 1) * 8) * 2;

    float d[8][4] = {};

    auto stage = [&](int c, int buf) {
#pragma unroll
        for (int l = 0; l < 2; l++) {
            int idx = t + l * 256;
            int n = idx >> 2, q = idx & 3;
            size_t go = (size_t)n * NN + c * 32 + q * 8;
            cp16(sB + (uint32_t)buf * 10240 + n * 80 + q * 16, Whh + go);
        }
        CP_COMMIT();
    };
    auto pgen = [&](int c, int buf) {
        int kb = c * 32 + kq * 8;
        unsigned w8 = mrow[c] >> (kq * 8);
        float4 b0 = *(const float4*)(cBp + kb);
        float4 b1 = *(const float4*)(cBp + kb + 4);
        float4 d0 = *(const float4*)(cDp + kb);
        float4 d1 = *(const float4*)(cDp + kb + 4);
        float p[8];
        p[0] = (w8 & 1u)   ? fmaxf(Ar * b0.x, Cr * d0.x) : 0.f;
        p[1] = (w8 & 2u)   ? fmaxf(Ar * b0.y, Cr * d0.y) : 0.f;
        p[2] = (w8 & 4u)   ? fmaxf(Ar * b0.z, Cr * d0.z) : 0.f;
        p[3] = (w8 & 8u)   ? fmaxf(Ar * b0.w, Cr * d0.w) : 0.f;
        p[4] = (w8 & 16u)  ? fmaxf(Ar * b1.x, Cr * d1.x) : 0.f;
        p[5] = (w8 & 32u)  ? fmaxf(Ar * b1.y, Cr * d1.y) : 0.f;
        p[6] = (w8 & 64u)  ? fmaxf(Ar * b1.z, Cr * d1.z) : 0.f;
        p[7] = (w8 & 128u) ? fmaxf(Ar * b1.w, Cr * d1.w) : 0.f;
        psum += ((p[0] + p[1]) + (p[2] + p[3])) + ((p[4] + p[5]) + (p[6] + p[7]));
        uint4 u;
        unsigned* ph = &u.x;
#pragma unroll
        for (int j = 0; j < 4; j++) {
            __half2 h2 = __floats2half2_rn(p[2 * j], p[2 * j + 1]);
            ph[j] = *(unsigned*)&h2;
        }
        *(uint4*)(smem + buf * 5120 + pr * 80 + kq * 16) = u;
    };

    stage(0, 0);
    pgen(0, 0);

    for (int c = 0; c < 128; c++) {
        int buf = c & 1;
        CP_WAIT0();
        __syncthreads();     // publish B(c), P(c); readers of buf^1 done
        if (c + 1 < 128) {
            stage(c + 1, buf ^ 1);   // overlaps with mma below
            pgen(c + 1, buf ^ 1);
        }
        uint32_t pH = sP + (uint32_t)buf * 5120;
        uint32_t bH = sB + (uint32_t)buf * 10240;
#pragma unroll
        for (int s = 0; s < 2; s++) {
            unsigned ah[4];
            ldsm_x4(ah, pH + a_off + s * 32);
#pragma unroll
            for (int pp = 0; pp < 4; pp++) {
                unsigned bh[4];
                uint32_t boff = b_roff + (uint32_t)(pp * 16) * (PSTR * 2) + b_koff + s * 32;
                ldsm_x4(bh, bH + boff);
                mma_f16(d[2 * pp],     ah, bh);
                mma_f16(d[2 * pp + 1], ah, bh + 2);
            }
        }
    }

    psum += __shfl_xor_sync(0xffffffffu, psum, 1);
    psum += __shfl_xor_sync(0xffffffffu, psum, 2);
    if (kq == 0) rsum[pr] = psum;
    __syncthreads();

    int rloc = wr * 16 + (lane >> 2);
    float inv0 = 1.f / rsum[rloc];
    float inv1 = 1.f / rsum[rloc + 8];
    int r0 = row0 + rloc;
    int cbase = h * 128 + wc * 64 + (lane & 3) * 2;
#pragma unroll
    for (int nt = 0; nt < 8; nt++) {
        int col = cbase + nt * 8;
        float v0 = d[nt][0] * inv0, v1 = d[nt][1] * inv0;
        float v2 = d[nt][2] * inv1, v3 = d[nt][3] * inv1;
        v0 = v0 > 0.f ? v0 : expm1f(v0);
        v1 = v1 > 0.f ? v1 : expm1f(v1);
        v2 = v2 > 0.f ? v2 : expm1f(v2);
        v3 = v3 > 0.f ? v3 : expm1f(v3);
        if (xhi) {
            __nv_bfloat16 h0 = __float2bfloat16(v0), h1 = __float2bfloat16(v1);
            __nv_bfloat16 h2 = __float2bfloat16(v2), h3 = __float2bfloat16(v3);
            __nv_bfloat16 l0 = __float2bfloat16(v0 - __bfloat162float(h0));
            __nv_bfloat16 l1 = __float2bfloat16(v1 - __bfloat162float(h1));
            __nv_bfloat16 l2 = __float2bfloat16(v2 - __bfloat162float(h2));
            __nv_bfloat16 l3 = __float2bfloat16(v3 - __bfloat162float(h3));
            *(__nv_bfloat162*)&xhi[(size_t)r0 * 512 + col] = __nv_bfloat162(h0, h1);
            *(__nv_bfloat162*)&xlo[(size_t)r0 * 512 + col] = __nv_bfloat162(l0, l1);
            *(__nv_bfloat162*)&xhi[(size_t)(r0 + 8) * 512 + col] = __nv_bfloat162(h2, h3);
            *(__nv_bfloat162*)&xlo[(size_t)(r0 + 8) * 512 + col] = __nv_bfloat162(l2, l3);
        } else {
            *(float2*)&out[(size_t)r0 * out_stride + col] = make_float2(v0, v1);
            *(float2*)&out[(size_t)(r0 + 8) * out_stride + col] = make_float2(v2, v3);
        }
    }
}

// ===========================================================================
extern "C" void kernel_launch(void* const* d_in, const int* in_sizes, int n_in,
                              void* d_out, int out_size) {
    const int* head = (const int*)d_in[0];
    const int* rel = (const int*)d_in[1];
    const float* adj = (const float*)d_in[2];
    const float* ee = (const float*)d_in[3];
    const float* re = (const float*)d_in[4];
    const float* W0 = (const float*)d_in[5];
    const float* a0 = (const float*)d_in[6];
    const float* Wm = (const float*)d_in[7];
    const float* am = (const float*)d_in[8];
    const float* Wo = (const float*)d_in[9];
    const float* ao = (const float*)d_in[10];
    float* out = (float*)d_out;

    float *f1, *f2, *fmax, *cB, *cD;
    __half* WhT;
    __nv_bfloat16 *Xhi, *Xlo, *Wth, *Wtl;
    unsigned* mask;
    cudaGetSymbolAddress((void**)&f1, g_f1);
    cudaGetSymbolAddress((void**)&f2, g_f2);
    cudaGetSymbolAddress((void**)&fmax, g_f2max);
    cudaGetSymbolAddress((void**)&cB, g_colB);
    cudaGetSymbolAddress((void**)&cD, g_colD);
    cudaGetSymbolAddress((void**)&WhT, g_WhT);
    cudaGetSymbolAddress((void**)&Xhi, g_Xhi);
    cudaGetSymbolAddress((void**)&Xlo, g_Xlo);
    cudaGetSymbolAddress((void**)&Wth, g_Wt_hi);
    cudaGetSymbolAddress((void**)&Wtl, g_Wt_lo);
    cudaGetSymbolAddress((void**)&mask, g_mask);

    cudaFuncSetAttribute(attn_mma_kernel, cudaFuncAttributeMaxDynamicSharedMemorySize, ATT_SMEM);
    cudaFuncSetAttribute(gemm_fused_kernel, cudaFuncAttributeMaxDynamicSharedMemorySize, GEMM_SMEM);

    build_mask_kernel<<<NN, 256>>>(adj, mask);
    hrc_kernel<<<NN, 128>>>(head, rel, ee, re, out + (size_t)NN * 128);
    split_kernel<<<(NN * 128 + 255) / 256, 256>>>(ee, Xhi, Xlo, NN * 128);
    wsplit_all_kernel<<<2432, 256>>>(W0, Wm, Wo, Wth, Wtl);

    // ---- layer 0: Fin = 128 ----
    gemm_fused_kernel<<<dim3(64, HH), 256, GEMM_SMEM>>>(Xhi, Xlo, Wth + WT_OFF0, Wtl + WT_OFF0,
                                                        a0, WhT, f1, f2, 128);
    maxprep_kernel<<<HH, 1024>>>(f2, cB, cD, fmax);
    attn_mma_kernel<<<dim3(64, HH), 256, ATT_SMEM>>>(WhT, f1, fmax, cB, cD, mask,
                                                     nullptr, 0, Xhi, Xlo);

    // ---- 9 middle layers: Fin = 512 ----
    for (int l = 0; l < NMID; l++) {
        gemm_fused_kernel<<<dim3(64, HH), 256, GEMM_SMEM>>>(Xhi, Xlo,
                                                            Wth + WT_OFFM(l), Wtl + WT_OFFM(l),
                                                            am + (size_t)l * HH * 256,
                                                            WhT, f1, f2, 512);
        maxprep_kernel<<<HH, 1024>>>(f2, cB, cD, fmax);
        attn_mma_kernel<<<dim3(64, HH), 256, ATT_SMEM>>>(WhT, f1, fmax, cB, cD, mask,
                                                         nullptr, 0, Xhi, Xlo);
    }

    // ---- output layer: 1 head, Fin = 512 ----
    gemm_fused_kernel<<<dim3(64, 1), 256, GEMM_SMEM>>>(Xhi, Xlo, Wth + WT_OFFO, Wtl + WT_OFFO,
                                                       ao, WhT, f1, f2, 512);
    maxprep_kernel<<<1, 1024>>>(f2, cB, cD, fmax);
    attn_mma_kernel<<<dim3(64, 1), 256, ATT_SMEM>>>(WhT, f1, fmax, cB, cD, mask,
                                                    out, 128, nullptr, nullptr);
}

// round 13
// speedup vs baseline: 2.4274x; 1.1473x over previous
#include <cuda_runtime.h>
#include <cuda_bf16.h>
#include <cuda_fp16.h>
#include <math.h>
#include <cstdint>

#define NN 4096
#define DD 128
#define HH 4
#define NMID 9
#define PSTR 40   // gemm: 16-bit elems per smem row (80B)
#define PSTR2 72  // attn: 16-bit elems per smem row (144B, 64-k chunks)

typedef unsigned long long u64;

// Wt (split weights) layout offsets, in elements
#define WT_OFF0 0
#define WT_OFFM(l) (65536 + (size_t)(l) * 262144)
#define WT_OFFO 2424832
#define WT_TOTAL 2490368

// ===========================================================================
// PTX helpers (sm_80-class: compiles for plain sm_103)
// ===========================================================================
__device__ __forceinline__ uint32_t smem_u32(const void* p) {
    uint32_t a;
    asm("{ .reg .u64 t; cvta.to.shared.u64 t, %1; cvt.u32.u64 %0, t; }" : "=r"(a) : "l"(p));
    return a;
}
__device__ __forceinline__ void ldsm_x4(unsigned* r, uint32_t addr) {
    asm volatile("ldmatrix.sync.aligned.m8n8.x4.shared.b16 {%0,%1,%2,%3}, [%4];"
                 : "=r"(r[0]), "=r"(r[1]), "=r"(r[2]), "=r"(r[3]) : "r"(addr));
}
__device__ __forceinline__ void mma_bf16(float* d, const unsigned* a, const unsigned* b) {
    asm volatile(
        "mma.sync.aligned.m16n8k16.row.col.f32.bf16.bf16.f32 "
        "{%0,%1,%2,%3}, {%4,%5,%6,%7}, {%8,%9}, {%0,%1,%2,%3};"
        : "+f"(d[0]), "+f"(d[1]), "+f"(d[2]), "+f"(d[3])
        : "r"(a[0]), "r"(a[1]), "r"(a[2]), "r"(a[3]), "r"(b[0]), "r"(b[1]));
}
__device__ __forceinline__ void mma_f16(float* d, const unsigned* a, const unsigned* b) {
    asm volatile(
        "mma.sync.aligned.m16n8k16.row.col.f32.f16.f16.f32 "
        "{%0,%1,%2,%3}, {%4,%5,%6,%7}, {%8,%9}, {%0,%1,%2,%3};"
        : "+f"(d[0]), "+f"(d[1]), "+f"(d[2]), "+f"(d[3])
        : "r"(a[0]), "r"(a[1]), "r"(a[2]), "r"(a[3]), "r"(b[0]), "r"(b[1]));
}
__device__ __forceinline__ void cp16(uint32_t dst, const void* src) {
    asm volatile("cp.async.ca.shared.global [%0], [%1], 16;" :: "r"(dst), "l"(src) : "memory");
}
#define CP_COMMIT() asm volatile("cp.async.commit_group;" ::: "memory")
#define CP_WAIT0()  asm volatile("cp.async.wait_group 0;" ::: "memory")

// ===========================================================================
// Scratch (device globals)
// ===========================================================================
__device__ __align__(16) __half g_WhT[HH * DD * NN];   // [h][n=128][k=4096] fp16
__device__ __align__(16) __nv_bfloat16 g_Xhi[NN * 512];
__device__ __align__(16) __nv_bfloat16 g_Xlo[NN * 512];
__device__ __align__(16) __nv_bfloat16 g_Wt_hi[WT_TOTAL];
__device__ __align__(16) __nv_bfloat16 g_Wt_lo[WT_TOTAL];
__device__ float g_f1[HH * NN];
__device__ float g_f2[HH * NN];
__device__ float g_f2max[HH];
__device__ __align__(16) float g_colB[HH * NN];
__device__ __align__(16) float g_colD[HH * NN];
__device__ unsigned g_mask[NN * 128];

// ===========================================================================
// adj > 0 -> bitmask
// ===========================================================================
__global__ void build_mask_kernel(const float* __restrict__ adj,
                                  unsigned* __restrict__ mask) {
    int i = blockIdx.x;
    int t = threadIdx.x;
    int lane = t & 31;
    const float* row = adj + (size_t)i * NN;
    for (int word = t >> 5; word < 128; word += 8) {
        float v = row[word * 32 + lane];
        unsigned b = __ballot_sync(0xffffffffu, v > 0.f);
        if (lane == 0) mask[i * 128 + word] = b;
    }
}

__global__ void hrc_kernel(const int* __restrict__ head, const int* __restrict__ rel,
                           const float* __restrict__ ee, const float* __restrict__ re,
                           float* __restrict__ out) {
    int i = blockIdx.x;
    int d = threadIdx.x;
    out[(size_t)i * 128 + d] =
        ee[(size_t)head[i] * 128 + d] + re[(size_t)rel[i] * 128 + d];
}

// ===========================================================================
// fp32 -> bf16 hi/lo split (flat) — layer-0 input (ee) only
// ===========================================================================
__global__ void split_kernel(const float* __restrict__ src,
                             __nv_bfloat16* __restrict__ hi,
                             __nv_bfloat16* __restrict__ lo, int n) {
    int i = blockIdx.x * 256 + threadIdx.x;
    if (i < n) {
        float v = src[i];
        __nv_bfloat16 h = __float2bfloat16(v);
        hi[i] = h;
        lo[i] = __float2bfloat16(v - __bfloat162float(h));
    }
}

// ===========================================================================
// ONE-SHOT weight transpose + bf16 split for ALL 11 layers. grid = 2432.
// ===========================================================================
__global__ void wsplit_all_kernel(const float* __restrict__ W0,
                                  const float* __restrict__ Wm,
                                  const float* __restrict__ Wo,
                                  __nv_bfloat16* __restrict__ dhi,
                                  __nv_bfloat16* __restrict__ dlo) {
    int b = blockIdx.x;
    const float* src;
    int kdim, kt, nt;
    size_t dst;
    if (b < 64) {
        int h = b >> 4, rem = b & 15;
        kt = rem >> 2; nt = rem & 3;
        src = W0 + (size_t)h * 128 * 128;
        kdim = 128;
        dst = WT_OFF0 + (size_t)h * 128 * 128;
    } else if (b < 2368) {
        int b2 = b - 64;
        int l = b2 >> 8, rem = b2 & 255;
        int h = rem >> 6, rem2 = rem & 63;
        kt = rem2 >> 2; nt = rem2 & 3;
        src = Wm + ((size_t)l * HH + h) * 512 * 128;
        kdim = 512;
        dst = WT_OFFM(l) + (size_t)h * 512 * 128;
    } else {
        int rem = b - 2368;
        kt = rem >> 2; nt = rem & 3;
        src = Wo;
        kdim = 512;
        dst = WT_OFFO;
    }
    int kbase = kt * 32, nbase = nt * 32;
    __shared__ float ts[32][33];
    int t = threadIdx.x;
#pragma unroll
    for (int l = 0; l < 4; l++) {
        int e = t + l * 256;
        int r = e >> 5, c = e & 31;
        ts[r][c] = src[(size_t)(kbase + r) * 128 + nbase + c];
    }
    __syncthreads();
#pragma unroll
    for (int l = 0; l < 4; l++) {
        int e = t + l * 256;
        int r = e >> 5, c = e & 31;
        float v = ts[c][r];
        __nv_bfloat16 hi = __float2bfloat16(v);
        __nv_bfloat16 lo = __float2bfloat16(v - __bfloat162float(hi));
        size_t o = dst + (size_t)(nbase + r) * kdim + kbase + c;
        dhi[o] = hi;
        dlo[o] = lo;
    }
}

// ===========================================================================
// FUSED GEMM (cp.async double-buffered): Wh_tile = X @ W (3-pass bf16 split);
// epilogue: f1/f2 row dots + transposed fp16 WhT write.
// smem: buf0 [0,30720), buf1 [30720,61440); epilogue reuses [0,34304).
// ===========================================================================
#define GEMM_SMEM 61440

__global__ void __launch_bounds__(256)
gemm_fused_kernel(const __nv_bfloat16* __restrict__ Xhi, const __nv_bfloat16* __restrict__ Xlo,
                  const __nv_bfloat16* __restrict__ WtHi, const __nv_bfloat16* __restrict__ WtLo,
                  const float* __restrict__ Avec,
                  __half* __restrict__ WhT,
                  float* __restrict__ f1g, float* __restrict__ f2g, int Fin) {
    extern __shared__ __align__(16) char smem[];
    uint32_t sb = smem_u32(smem);

    int h = blockIdx.y;
    int row0 = blockIdx.x * 64;
    int t = threadIdx.x, wid = t >> 5, lane = t & 31;
    int wr = wid & 3, wc = wid >> 2;
    const __nv_bfloat16* Wth = WtHi + (size_t)h * 128 * Fin;
    const __nv_bfloat16* Wtl = WtLo + (size_t)h * 128 * Fin;

    float d[8][4] = {};

    uint32_t a_off = (uint32_t)(wr * 16 + ((lane >> 3) & 1) * 8 + (lane & 7)) * (PSTR * 2)
                   + (uint32_t)((lane >> 4) * 8) * 2;
    uint32_t b_roff = (uint32_t)(wc * 64 + (lane >> 4) * 8 + (lane & 7)) * (PSTR * 2);
    uint32_t b_koff = (uint32_t)(((lane >> 3) & 1) * 8) * 2;

    auto stage = [&](int k0, int buf) {
        uint32_t base = sb + (uint32_t)buf * 30720;
        {
            int m = t >> 2, q = t & 3;
            size_t go = (size_t)(row0 + m) * Fin + k0 + q * 8;
            cp16(base + 0    + m * 80 + q * 16, Xhi + go);
            cp16(base + 5120 + m * 80 + q * 16, Xlo + go);
        }
#pragma unroll
        for (int l = 0; l < 2; l++) {
            int idx = t + l * 256;
            int n = idx >> 2, q = idx & 3;
            size_t go = (size_t)n * Fin + k0 + q * 8;
            cp16(base + 10240 + n * 80 + q * 16, Wth + go);
            cp16(base + 20480 + n * 80 + q * 16, Wtl + go);
        }
        CP_COMMIT();
    };

    int nIter = Fin >> 5;
    stage(0, 0);
    for (int it = 0; it < nIter; it++) {
        int buf = it & 1;
        CP_WAIT0();
        __syncthreads();     // publish tiles(it); readers of buf^1 done
        if (it + 1 < nIter) stage((it + 1) * 32, buf ^ 1);
        uint32_t base = sb + (uint32_t)buf * 30720;
        uint32_t sAhi = base, sAlo = base + 5120;
        uint32_t sBhi = base + 10240, sBlo = base + 20480;
#pragma unroll
        for (int s = 0; s < 2; s++) {
            unsigned ah[4], al[4];
            ldsm_x4(ah, sAhi + a_off + s * 32);
            ldsm_x4(al, sAlo + a_off + s * 32);
#pragma unroll
            for (int pp = 0; pp < 4; pp++) {
                unsigned bh[4], bl[4];
                uint32_t boff = b_roff + (uint32_t)(pp * 16) * (PSTR * 2) + b_koff + s * 32;
                ldsm_x4(bh, sBhi + boff);
                ldsm_x4(bl, sBlo + boff);
                mma_bf16(d[2 * pp],     ah, bh);
                mma_bf16(d[2 * pp + 1], ah, bh + 2);
                mma_bf16(d[2 * pp],     ah, bl);
                mma_bf16(d[2 * pp + 1], ah, bl + 2);
                mma_bf16(d[2 * pp],     al, bh);
                mma_bf16(d[2 * pp + 1], al, bh + 2);
            }
        }
    }

    // ------- fused epilogue -------
    __syncthreads();   // all ldsm reads done; smem re-purposed
    float* Ws = (float*)smem;              // [64][130]
    float* fr = (float*)(smem + 33280);    // [2][2][64]
    const float* av = Avec + h * 256;

    int rloc = wr * 16 + (lane >> 2);
    int cb = wc * 64 + (lane & 3) * 2;
    float s1a = 0.f, s2a = 0.f, s1b = 0.f, s2b = 0.f;
#pragma unroll
    for (int nt = 0; nt < 8; nt++) {
        int col = cb + nt * 8;
        float a1x = av[col], a1y = av[col + 1];
        float a2x = av[128 + col], a2y = av[128 + col + 1];
        float d0 = d[nt][0], d1 = d[nt][1], d2 = d[nt][2], d3 = d[nt][3];
        Ws[rloc * 130 + col] = d0;
        Ws[rloc * 130 + col + 1] = d1;
        Ws[(rloc + 8) * 130 + col] = d2;
        Ws[(rloc + 8) * 130 + col + 1] = d3;
        s1a += d0 * a1x + d1 * a1y;
        s2a += d0 * a2x + d1 * a2y;
        s1b += d2 * a1x + d3 * a1y;
        s2b += d2 * a2x + d3 * a2y;
    }
#pragma unroll
    for (int o = 1; o <= 2; o <<= 1) {
        s1a += __shfl_xor_sync(0xffffffffu, s1a, o);
        s2a += __shfl_xor_sync(0xffffffffu, s2a, o);
        s1b += __shfl_xor_sync(0xffffffffu, s1b, o);
        s2b += __shfl_xor_sync(0xffffffffu, s2b, o);
    }
    if ((lane & 3) == 0) {
        fr[(0 * 2 + wc) * 64 + rloc] = s1a;
        fr[(0 * 2 + wc) * 64 + rloc + 8] = s1b;
        fr[(1 * 2 + wc) * 64 + rloc] = s2a;
        fr[(1 * 2 + wc) * 64 + rloc + 8] = s2b;
    }
    __syncthreads();
    if (t < 64) {
        f1g[h * NN + row0 + t] = fr[0 * 64 + t] + fr[1 * 64 + t];
        f2g[h * NN + row0 + t] = fr[2 * 64 + t] + fr[3 * 64 + t];
    }

#pragma unroll
    for (int i = 0; i < 4; i++) {
        int n = t >> 1, kg = 4 * (t & 1) + i;
        __half hv[8];
#pragma unroll
        for (int j = 0; j < 8; j++)
            hv[j] = __float2half_rn(Ws[(kg * 8 + j) * 130 + n]);
        size_t o = (size_t)(h * 128 + n) * NN + row0 + kg * 8;
        *(uint4*)&WhT[o] = *(uint4*)hv;
    }
}

// ===========================================================================
// merged: colB = exp(f2), colD = exp(0.2 f2), fmax[h] = max f2  (grid = H)
// ===========================================================================
__global__ void maxprep_kernel(const float* __restrict__ f2,
                               float* __restrict__ colB, float* __restrict__ colD,
                               float* __restrict__ fmax) {
    int h = blockIdx.x;
    __shared__ float red[32];
    float m = -1e30f;
#pragma unroll
    for (int l = 0; l < 4; l++) {
        int i = threadIdx.x + l * 1024;
        int idx = h * NN + i;
        float b = f2[idx];
        colB[idx] = __expf(b);
        colD[idx] = __expf(0.2f * b);
        m = fmaxf(m, b);
    }
#pragma unroll
    for (int o = 16; o; o >>= 1) m = fmaxf(m, __shfl_xor_sync(0xffffffffu, m, o));
    if ((threadIdx.x & 31) == 0) red[threadIdx.x >> 5] = m;
    __syncthreads();
    if (threadIdx.x < 32) {
        m = red[threadIdx.x];
#pragma unroll
        for (int o = 16; o; o >>= 1) m = fmaxf(m, __shfl_xor_sync(0xffffffffu, m, o));
        if (threadIdx.x == 0) fmax[h] = m;
    }
}

// ===========================================================================
// Pipelined mma.sync attention, single-pass fp16, 64-k chunks.
// CTA 64m x 128n, grid (64, H). smem (144B rows):
//   P[buf]: buf*9216   (64 x 144B)   total 18432
//   B[buf]: 18432 + buf*18432 (128 x 144B) total 36864
//   rowsum: 55296 (64 floats)
// ===========================================================================
#define ATT_SMEM 55552

__global__ void __launch_bounds__(256)
attn_mma_kernel(const __half* __restrict__ WhT,
                const float* __restrict__ f1v, const float* __restrict__ f2max,
                const float* __restrict__ colB, const float* __restrict__ colD,
                const unsigned* __restrict__ mask,
                float* __restrict__ out, int out_stride,
                __nv_bfloat16* __restrict__ xhi, __nv_bfloat16* __restrict__ xlo) {
    extern __shared__ __align__(16) char smem[];
    uint32_t sb = smem_u32(smem);
    const uint32_t sP = sb;
    const uint32_t sB = sb + 18432;
    float* rsum = (float*)(smem + 55296);

    int h = blockIdx.y;
    int row0 = blockIdx.x * 64;
    int hbase = h * NN;
    int t = threadIdx.x, wid = t >> 5, lane = t & 31;
    int wr = wid & 3, wc = wid >> 2;

    const __half* Whh = WhT + (size_t)(h * 128) * NN;

    // P-gen role: thread covers row pr (0..63), two k-octets kq0, kq0+1
    int pr = t >> 2, kq0 = (t & 3) * 2;
    float f1r = f1v[hbase + row0 + pr];
    float mF2 = f2max[h];
    float xm = f1r + mF2;
    float m = xm > 0.f ? xm : 0.2f * xm;
    float Ar = __expf(f1r - m);
    float Cr = __expf(0.2f * f1r - m);
    float psum = 0.f;

    const unsigned* mrow = mask + (size_t)(row0 + pr) * 128;
    const float* cBp = colB + hbase;
    const float* cDp = colD + hbase;

    uint32_t a_off = (uint32_t)(wr * 16 + ((lane >> 3) & 1) * 8 + (lane & 7)) * (PSTR2 * 2)
                   + (uint32_t)((lane >> 4) * 8) * 2;
    uint32_t b_roff = (uint32_t)(wc * 64 + (lane >> 4) * 8 + (lane & 7)) * (PSTR2 * 2);
    uint32_t b_koff = (uint32_t)(((lane >> 3) & 1) * 8) * 2;

    float d[8][4] = {};

    auto stage = [&](int c, int buf) {
        // 128 rows x 64k fp16 = 16KB -> 4 cp16 per thread
#pragma unroll
        for (int l = 0; l < 4; l++) {
            int idx = t + l * 256;
            int n = idx >> 3, q = idx & 7;
            size_t go = (size_t)n * NN + c * 64 + q * 8;
            cp16(sB + (uint32_t)buf * 18432 + n * 144 + q * 16, Whh + go);
        }
        CP_COMMIT();
    };
    auto pgen = [&](int c, int buf) {
        unsigned wrd = mrow[2 * c + (kq0 >> 2)];
#pragma unroll
        for (int j2 = 0; j2 < 2; j2++) {
            int o = kq0 + j2;
            int kb = c * 64 + o * 8;
            unsigned w8 = wrd >> ((o & 3) * 8);
            float4 b0 = *(const float4*)(cBp + kb);
            float4 b1 = *(const float4*)(cBp + kb + 4);
            float4 d0 = *(const float4*)(cDp + kb);
            float4 d1 = *(const float4*)(cDp + kb + 4);
            float p[8];
            p[0] = (w8 & 1u)   ? fmaxf(Ar * b0.x, Cr * d0.x) : 0.f;
            p[1] = (w8 & 2u)   ? fmaxf(Ar * b0.y, Cr * d0.y) : 0.f;
            p[2] = (w8 & 4u)   ? fmaxf(Ar * b0.z, Cr * d0.z) : 0.f;
            p[3] = (w8 & 8u)   ? fmaxf(Ar * b0.w, Cr * d0.w) : 0.f;
            p[4] = (w8 & 16u)  ? fmaxf(Ar * b1.x, Cr * d1.x) : 0.f;
            p[5] = (w8 & 32u)  ? fmaxf(Ar * b1.y, Cr * d1.y) : 0.f;
            p[6] = (w8 & 64u)  ? fmaxf(Ar * b1.z, Cr * d1.z) : 0.f;
            p[7] = (w8 & 128u) ? fmaxf(Ar * b1.w, Cr * d1.w) : 0.f;
            psum += ((p[0] + p[1]) + (p[2] + p[3])) + ((p[4] + p[5]) + (p[6] + p[7]));
            uint4 u;
            unsigned* ph = &u.x;
#pragma unroll
            for (int j = 0; j < 4; j++) {
                __half2 h2 = __floats2half2_rn(p[2 * j], p[2 * j + 1]);
                ph[j] = *(unsigned*)&h2;
            }
            *(uint4*)(smem + buf * 9216 + pr * 144 + o * 16) = u;
        }
    };

    stage(0, 0);
    pgen(0, 0);

    for (int c = 0; c < 64; c++) {
        int buf = c & 1;
        CP_WAIT0();
        __syncthreads();     // publish B(c), P(c); readers of buf^1 done
        if (c + 1 < 64) {
            stage(c + 1, buf ^ 1);   // overlaps with mma below
            pgen(c + 1, buf ^ 1);
        }
        uint32_t pH = sP + (uint32_t)buf * 9216;
        uint32_t bH = sB + (uint32_t)buf * 18432;
#pragma unroll
        for (int s = 0; s < 4; s++) {
            unsigned ah[4];
            ldsm_x4(ah, pH + a_off + s * 32);
#pragma unroll
            for (int pp = 0; pp < 4; pp++) {
                unsigned bh[4];
                uint32_t boff = b_roff + (uint32_t)(pp * 16) * (PSTR2 * 2) + b_koff + s * 32;
                ldsm_x4(bh, bH + boff);
                mma_f16(d[2 * pp],     ah, bh);
                mma_f16(d[2 * pp + 1], ah, bh + 2);
            }
        }
    }

    psum += __shfl_xor_sync(0xffffffffu, psum, 1);
    psum += __shfl_xor_sync(0xffffffffu, psum, 2);
    if ((t & 3) == 0) rsum[pr] = psum;
    __syncthreads();

    int rloc = wr * 16 + (lane >> 2);
    float inv0 = 1.f / rsum[rloc];
    float inv1 = 1.f / rsum[rloc + 8];
    int r0 = row0 + rloc;
    int cbase = h * 128 + wc * 64 + (lane & 3) * 2;
#pragma unroll
    for (int nt = 0; nt < 8; nt++) {
        int col = cbase + nt * 8;
        float v0 = d[nt][0] * inv0, v1 = d[nt][1] * inv0;
        float v2 = d[nt][2] * inv1, v3 = d[nt][3] * inv1;
        v0 = v0 > 0.f ? v0 : expm1f(v0);
        v1 = v1 > 0.f ? v1 : expm1f(v1);
        v2 = v2 > 0.f ? v2 : expm1f(v2);
        v3 = v3 > 0.f ? v3 : expm1f(v3);
        if (xhi) {
            __nv_bfloat16 h0 = __float2bfloat16(v0), h1 = __float2bfloat16(v1);
            __nv_bfloat16 h2 = __float2bfloat16(v2), h3 = __float2bfloat16(v3);
            __nv_bfloat16 l0 = __float2bfloat16(v0 - __bfloat162float(h0));
            __nv_bfloat16 l1 = __float2bfloat16(v1 - __bfloat162float(h1));
            __nv_bfloat16 l2 = __float2bfloat16(v2 - __bfloat162float(h2));
            __nv_bfloat16 l3 = __float2bfloat16(v3 - __bfloat162float(h3));
            *(__nv_bfloat162*)&xhi[(size_t)r0 * 512 + col] = __nv_bfloat162(h0, h1);
            *(__nv_bfloat162*)&xlo[(size_t)r0 * 512 + col] = __nv_bfloat162(l0, l1);
            *(__nv_bfloat162*)&xhi[(size_t)(r0 + 8) * 512 + col] = __nv_bfloat162(h2, h3);
            *(__nv_bfloat162*)&xlo[(size_t)(r0 + 8) * 512 + col] = __nv_bfloat162(l2, l3);
        } else {
            *(float2*)&out[(size_t)r0 * out_stride + col] = make_float2(v0, v1);
            *(float2*)&out[(size_t)(r0 + 8) * out_stride + col] = make_float2(v2, v3);
        }
    }
}

// ===========================================================================
extern "C" void kernel_launch(void* const* d_in, const int* in_sizes, int n_in,
                              void* d_out, int out_size) {
    const int* head = (const int*)d_in[0];
    const int* rel = (const int*)d_in[1];
    const float* adj = (const float*)d_in[2];
    const float* ee = (const float*)d_in[3];
    const float* re = (const float*)d_in[4];
    const float* W0 = (const float*)d_in[5];
    const float* a0 = (const float*)d_in[6];
    const float* Wm = (const float*)d_in[7];
    const float* am = (const float*)d_in[8];
    const float* Wo = (const float*)d_in[9];
    const float* ao = (const float*)d_in[10];
    float* out = (float*)d_out;

    float *f1, *f2, *fmax, *cB, *cD;
    __half* WhT;
    __nv_bfloat16 *Xhi, *Xlo, *Wth, *Wtl;
    unsigned* mask;
    cudaGetSymbolAddress((void**)&f1, g_f1);
    cudaGetSymbolAddress((void**)&f2, g_f2);
    cudaGetSymbolAddress((void**)&fmax, g_f2max);
    cudaGetSymbolAddress((void**)&cB, g_colB);
    cudaGetSymbolAddress((void**)&cD, g_colD);
    cudaGetSymbolAddress((void**)&WhT, g_WhT);
    cudaGetSymbolAddress((void**)&Xhi, g_Xhi);
    cudaGetSymbolAddress((void**)&Xlo, g_Xlo);
    cudaGetSymbolAddress((void**)&Wth, g_Wt_hi);
    cudaGetSymbolAddress((void**)&Wtl, g_Wt_lo);
    cudaGetSymbolAddress((void**)&mask, g_mask);

    cudaFuncSetAttribute(attn_mma_kernel, cudaFuncAttributeMaxDynamicSharedMemorySize, ATT_SMEM);
    cudaFuncSetAttribute(gemm_fused_kernel, cudaFuncAttributeMaxDynamicSharedMemorySize, GEMM_SMEM);

    build_mask_kernel<<<NN, 256>>>(adj, mask);
    hrc_kernel<<<NN, 128>>>(head, rel, ee, re, out + (size_t)NN * 128);
    split_kernel<<<(NN * 128 + 255) / 256, 256>>>(ee, Xhi, Xlo, NN * 128);
    wsplit_all_kernel<<<2432, 256>>>(W0, Wm, Wo, Wth, Wtl);

    // ---- layer 0: Fin = 128 ----
    gemm_fused_kernel<<<dim3(64, HH), 256, GEMM_SMEM>>>(Xhi, Xlo, Wth + WT_OFF0, Wtl + WT_OFF0,
                                                        a0, WhT, f1, f2, 128);
    maxprep_kernel<<<HH, 1024>>>(f2, cB, cD, fmax);
    attn_mma_kernel<<<dim3(64, HH), 256, ATT_SMEM>>>(WhT, f1, fmax, cB, cD, mask,
                                                     nullptr, 0, Xhi, Xlo);

    // ---- 9 middle layers: Fin = 512 ----
    for (int l = 0; l < NMID; l++) {
        gemm_fused_kernel<<<dim3(64, HH), 256, GEMM_SMEM>>>(Xhi, Xlo,
                                                            Wth + WT_OFFM(l), Wtl + WT_OFFM(l),
                                                            am + (size_t)l * HH * 256,
                                                            WhT, f1, f2, 512);
        maxprep_kernel<<<HH, 1024>>>(f2, cB, cD, fmax);
        attn_mma_kernel<<<dim3(64, HH), 256, ATT_SMEM>>>(WhT, f1, fmax, cB, cD, mask,
                                                         nullptr, 0, Xhi, Xlo);
    }

    // ---- output layer: 1 head, Fin = 512 ----
    gemm_fused_kernel<<<dim3(64, 1), 256, GEMM_SMEM>>>(Xhi, Xlo, Wth + WT_OFFO, Wtl + WT_OFFO,
                                                       ao, WhT, f1, f2, 512);
    maxprep_kernel<<<1, 1024>>>(f2, cB, cD, fmax);
    attn_mma_kernel<<<dim3(64, 1), 256, ATT_SMEM>>>(WhT, f1, fmax, cB, cD, mask,
                                                    out, 128, nullptr, nullptr);
}

// round 14
// speedup vs baseline: 2.4544x; 1.0111x over previous
#include <cuda_runtime.h>
#include <cuda_bf16.h>
#include <cuda_fp16.h>
#include <math.h>
#include <cstdint>

#define NN 4096
#define DD 128
#define HH 4
#define NMID 9
#define PSTR 40   // gemm: 16-bit elems per smem row (80B)
#define PSTR2 72  // attn: 16-bit elems per smem row (144B, 64-k chunks)

typedef unsigned long long u64;

// Wt (split weights) layout offsets, in elements
#define WT_OFF0 0
#define WT_OFFM(l) (65536 + (size_t)(l) * 262144)
#define WT_OFFO 2424832
#define WT_TOTAL 2490368

// ===========================================================================
// PTX helpers (sm_80-class: compiles for plain sm_103)
// ===========================================================================
__device__ __forceinline__ uint32_t smem_u32(const void* p) {
    uint32_t a;
    asm("{ .reg .u64 t; cvta.to.shared.u64 t, %1; cvt.u32.u64 %0, t; }" : "=r"(a) : "l"(p));
    return a;
}
__device__ __forceinline__ void ldsm_x4(unsigned* r, uint32_t addr) {
    asm volatile("ldmatrix.sync.aligned.m8n8.x4.shared.b16 {%0,%1,%2,%3}, [%4];"
                 : "=r"(r[0]), "=r"(r[1]), "=r"(r[2]), "=r"(r[3]) : "r"(addr));
}
__device__ __forceinline__ void mma_bf16(float* d, const unsigned* a, const unsigned* b) {
    asm volatile(
        "mma.sync.aligned.m16n8k16.row.col.f32.bf16.bf16.f32 "
        "{%0,%1,%2,%3}, {%4,%5,%6,%7}, {%8,%9}, {%0,%1,%2,%3};"
        : "+f"(d[0]), "+f"(d[1]), "+f"(d[2]), "+f"(d[3])
        : "r"(a[0]), "r"(a[1]), "r"(a[2]), "r"(a[3]), "r"(b[0]), "r"(b[1]));
}
__device__ __forceinline__ void mma_f16(float* d, const unsigned* a, const unsigned* b) {
    asm volatile(
        "mma.sync.aligned.m16n8k16.row.col.f32.f16.f16.f32 "
        "{%0,%1,%2,%3}, {%4,%5,%6,%7}, {%8,%9}, {%0,%1,%2,%3};"
        : "+f"(d[0]), "+f"(d[1]), "+f"(d[2]), "+f"(d[3])
        : "r"(a[0]), "r"(a[1]), "r"(a[2]), "r"(a[3]), "r"(b[0]), "r"(b[1]));
}
__device__ __forceinline__ void cp16(uint32_t dst, const void* src) {
    asm volatile("cp.async.ca.shared.global [%0], [%1], 16;" :: "r"(dst), "l"(src) : "memory");
}
#define CP_COMMIT() asm volatile("cp.async.commit_group;" ::: "memory")
#define CP_WAIT0()  asm volatile("cp.async.wait_group 0;" ::: "memory")

// ===========================================================================
// Scratch (device globals)
// ===========================================================================
__device__ __align__(16) __half g_WhT[HH * DD * NN];   // [h][n=128][k=4096] fp16
__device__ __align__(16) __nv_bfloat16 g_Xhi[NN * 512];
__device__ __align__(16) __nv_bfloat16 g_Xlo[NN * 512];
__device__ __align__(16) __nv_bfloat16 g_Wt_hi[WT_TOTAL];
__device__ __align__(16) __nv_bfloat16 g_Wt_lo[WT_TOTAL];
__device__ float g_f1[HH * NN];
__device__ float g_fmaxp[HH * 64];   // per-CTA f2 max partials
__device__ __align__(16) float g_colB[HH * NN];
__device__ __align__(16) float g_colD[HH * NN];
__device__ unsigned g_mask[NN * 128];

// ===========================================================================
// adj > 0 -> bitmask
// ===========================================================================
__global__ void build_mask_kernel(const float* __restrict__ adj,
                                  unsigned* __restrict__ mask) {
    int i = blockIdx.x;
    int t = threadIdx.x;
    int lane = t & 31;
    const float* row = adj + (size_t)i * NN;
    for (int word = t >> 5; word < 128; word += 8) {
        float v = row[word * 32 + lane];
        unsigned b = __ballot_sync(0xffffffffu, v > 0.f);
        if (lane == 0) mask[i * 128 + word] = b;
    }
}

__global__ void hrc_kernel(const int* __restrict__ head, const int* __restrict__ rel,
                           const float* __restrict__ ee, const float* __restrict__ re,
                           float* __restrict__ out) {
    int i = blockIdx.x;
    int d = threadIdx.x;
    out[(size_t)i * 128 + d] =
        ee[(size_t)head[i] * 128 + d] + re[(size_t)rel[i] * 128 + d];
}

// ===========================================================================
// fp32 -> bf16 hi/lo split (flat) — layer-0 input (ee) only
// ===========================================================================
__global__ void split_kernel(const float* __restrict__ src,
                             __nv_bfloat16* __restrict__ hi,
                             __nv_bfloat16* __restrict__ lo, int n) {
    int i = blockIdx.x * 256 + threadIdx.x;
    if (i < n) {
        float v = src[i];
        __nv_bfloat16 h = __float2bfloat16(v);
        hi[i] = h;
        lo[i] = __float2bfloat16(v - __bfloat162float(h));
    }
}

// ===========================================================================
// ONE-SHOT weight transpose + bf16 split for ALL 11 layers. grid = 2432.
// ===========================================================================
__global__ void wsplit_all_kernel(const float* __restrict__ W0,
                                  const float* __restrict__ Wm,
                                  const float* __restrict__ Wo,
                                  __nv_bfloat16* __restrict__ dhi,
                                  __nv_bfloat16* __restrict__ dlo) {
    int b = blockIdx.x;
    const float* src;
    int kdim, kt, nt;
    size_t dst;
    if (b < 64) {
        int h = b >> 4, rem = b & 15;
        kt = rem >> 2; nt = rem & 3;
        src = W0 + (size_t)h * 128 * 128;
        kdim = 128;
        dst = WT_OFF0 + (size_t)h * 128 * 128;
    } else if (b < 2368) {
        int b2 = b - 64;
        int l = b2 >> 8, rem = b2 & 255;
        int h = rem >> 6, rem2 = rem & 63;
        kt = rem2 >> 2; nt = rem2 & 3;
        src = Wm + ((size_t)l * HH + h) * 512 * 128;
        kdim = 512;
        dst = WT_OFFM(l) + (size_t)h * 512 * 128;
    } else {
        int rem = b - 2368;
        kt = rem >> 2; nt = rem & 3;
        src = Wo;
        kdim = 512;
        dst = WT_OFFO;
    }
    int kbase = kt * 32, nbase = nt * 32;
    __shared__ float ts[32][33];
    int t = threadIdx.x;
#pragma unroll
    for (int l = 0; l < 4; l++) {
        int e = t + l * 256;
        int r = e >> 5, c = e & 31;
        ts[r][c] = src[(size_t)(kbase + r) * 128 + nbase + c];
    }
    __syncthreads();
#pragma unroll
    for (int l = 0; l < 4; l++) {
        int e = t + l * 256;
        int r = e >> 5, c = e & 31;
        float v = ts[c][r];
        __nv_bfloat16 hi = __float2bfloat16(v);
        __nv_bfloat16 lo = __float2bfloat16(v - __bfloat162float(hi));
        size_t o = dst + (size_t)(nbase + r) * kdim + kbase + c;
        dhi[o] = hi;
        dlo[o] = lo;
    }
}

// ===========================================================================
// FUSED GEMM (cp.async double-buffered): Wh_tile = X @ W (3-pass bf16 split);
// epilogue: f1 + colB/colD + f2-max partial + transposed fp16 WhT write.
// smem: buf0 [0,30720), buf1 [30720,61440); epilogue reuses [0,34336).
// ===========================================================================
#define GEMM_SMEM 61440

__global__ void __launch_bounds__(256)
gemm_fused_kernel(const __nv_bfloat16* __restrict__ Xhi, const __nv_bfloat16* __restrict__ Xlo,
                  const __nv_bfloat16* __restrict__ WtHi, const __nv_bfloat16* __restrict__ WtLo,
                  const float* __restrict__ Avec,
                  __half* __restrict__ WhT, float* __restrict__ f1g,
                  float* __restrict__ colB, float* __restrict__ colD,
                  float* __restrict__ fmaxp, int Fin) {
    extern __shared__ __align__(16) char smem[];
    uint32_t sb = smem_u32(smem);

    int h = blockIdx.y;
    int row0 = blockIdx.x * 64;
    int t = threadIdx.x, wid = t >> 5, lane = t & 31;
    int wr = wid & 3, wc = wid >> 2;
    const __nv_bfloat16* Wth = WtHi + (size_t)h * 128 * Fin;
    const __nv_bfloat16* Wtl = WtLo + (size_t)h * 128 * Fin;

    float d[8][4] = {};

    uint32_t a_off = (uint32_t)(wr * 16 + ((lane >> 3) & 1) * 8 + (lane & 7)) * (PSTR * 2)
                   + (uint32_t)((lane >> 4) * 8) * 2;
    uint32_t b_roff = (uint32_t)(wc * 64 + (lane >> 4) * 8 + (lane & 7)) * (PSTR * 2);
    uint32_t b_koff = (uint32_t)(((lane >> 3) & 1) * 8) * 2;

    auto stage = [&](int k0, int buf) {
        uint32_t base = sb + (uint32_t)buf * 30720;
        {
            int m = t >> 2, q = t & 3;
            size_t go = (size_t)(row0 + m) * Fin + k0 + q * 8;
            cp16(base + 0    + m * 80 + q * 16, Xhi + go);
            cp16(base + 5120 + m * 80 + q * 16, Xlo + go);
        }
#pragma unroll
        for (int l = 0; l < 2; l++) {
            int idx = t + l * 256;
            int n = idx >> 2, q = idx & 3;
            size_t go = (size_t)n * Fin + k0 + q * 8;
            cp16(base + 10240 + n * 80 + q * 16, Wth + go);
            cp16(base + 20480 + n * 80 + q * 16, Wtl + go);
        }
        CP_COMMIT();
    };

    int nIter = Fin >> 5;
    stage(0, 0);
    for (int it = 0; it < nIter; it++) {
        int buf = it & 1;
        CP_WAIT0();
        __syncthreads();     // publish tiles(it); readers of buf^1 done
        if (it + 1 < nIter) stage((it + 1) * 32, buf ^ 1);
        uint32_t base = sb + (uint32_t)buf * 30720;
        uint32_t sAhi = base, sAlo = base + 5120;
        uint32_t sBhi = base + 10240, sBlo = base + 20480;
#pragma unroll
        for (int s = 0; s < 2; s++) {
            unsigned ah[4], al[4];
            ldsm_x4(ah, sAhi + a_off + s * 32);
            ldsm_x4(al, sAlo + a_off + s * 32);
#pragma unroll
            for (int pp = 0; pp < 4; pp++) {
                unsigned bh[4], bl[4];
                uint32_t boff = b_roff + (uint32_t)(pp * 16) * (PSTR * 2) + b_koff + s * 32;
                ldsm_x4(bh, sBhi + boff);
                ldsm_x4(bl, sBlo + boff);
                mma_bf16(d[2 * pp],     ah, bh);
                mma_bf16(d[2 * pp + 1], ah, bh + 2);
                mma_bf16(d[2 * pp],     ah, bl);
                mma_bf16(d[2 * pp + 1], ah, bl + 2);
                mma_bf16(d[2 * pp],     al, bh);
                mma_bf16(d[2 * pp + 1], al, bh + 2);
            }
        }
    }

    // ------- fused epilogue -------
    __syncthreads();   // all ldsm reads done; smem re-purposed
    float* Ws = (float*)smem;              // [64][130]
    float* fr = (float*)(smem + 33280);    // [2][2][64]
    float* sc = (float*)(smem + 34304);    // [2] per-warp f2 maxes
    const float* av = Avec + h * 256;

    int rloc = wr * 16 + (lane >> 2);
    int cb = wc * 64 + (lane & 3) * 2;
    float s1a = 0.f, s2a = 0.f, s1b = 0.f, s2b = 0.f;
#pragma unroll
    for (int nt = 0; nt < 8; nt++) {
        int col = cb + nt * 8;
        float a1x = av[col], a1y = av[col + 1];
        float a2x = av[128 + col], a2y = av[128 + col + 1];
        float d0 = d[nt][0], d1 = d[nt][1], d2 = d[nt][2], d3 = d[nt][3];
        Ws[rloc * 130 + col] = d0;
        Ws[rloc * 130 + col + 1] = d1;
        Ws[(rloc + 8) * 130 + col] = d2;
        Ws[(rloc + 8) * 130 + col + 1] = d3;
        s1a += d0 * a1x + d1 * a1y;
        s2a += d0 * a2x + d1 * a2y;
        s1b += d2 * a1x + d3 * a1y;
        s2b += d2 * a2x + d3 * a2y;
    }
#pragma unroll
    for (int o = 1; o <= 2; o <<= 1) {
        s1a += __shfl_xor_sync(0xffffffffu, s1a, o);
        s2a += __shfl_xor_sync(0xffffffffu, s2a, o);
        s1b += __shfl_xor_sync(0xffffffffu, s1b, o);
        s2b += __shfl_xor_sync(0xffffffffu, s2b, o);
    }
    if ((lane & 3) == 0) {
        fr[(0 * 2 + wc) * 64 + rloc] = s1a;
        fr[(0 * 2 + wc) * 64 + rloc + 8] = s1b;
        fr[(1 * 2 + wc) * 64 + rloc] = s2a;
        fr[(1 * 2 + wc) * 64 + rloc + 8] = s2b;
    }
    __syncthreads();
    if (t < 64) {
        float v1 = fr[0 * 64 + t] + fr[1 * 64 + t];
        float v2 = fr[2 * 64 + t] + fr[3 * 64 + t];
        int idx = h * NN + row0 + t;
        f1g[idx] = v1;
        colB[idx] = __expf(v2);
        colD[idx] = __expf(0.2f * v2);
        // warp-max of v2 over warps 0,1 (fully active)
        float mm = v2;
#pragma unroll
        for (int o = 16; o; o >>= 1) mm = fmaxf(mm, __shfl_xor_sync(0xffffffffu, mm, o));
        if (lane == 0) sc[wid] = mm;
    }

    // transposed fp16 write (reads Ws; disjoint from fr/sc)
#pragma unroll
    for (int i = 0; i < 4; i++) {
        int n = t >> 1, kg = 4 * (t & 1) + i;
        __half hv[8];
#pragma unroll
        for (int j = 0; j < 8; j++)
            hv[j] = __float2half_rn(Ws[(kg * 8 + j) * 130 + n]);
        size_t o = (size_t)(h * 128 + n) * NN + row0 + kg * 8;
        *(uint4*)&WhT[o] = *(uint4*)hv;
    }
    __syncthreads();
    if (t == 0) fmaxp[h * 64 + blockIdx.x] = fmaxf(sc[0], sc[1]);
}

// ===========================================================================
// Pipelined mma.sync attention, single-pass fp16, 64-k chunks.
// Loop order: stage(c+1) -> mma(c) -> pgen(c+1) for latency overlap.
// CTA 64m x 128n, grid (64, H). smem (144B rows):
//   P[buf]: buf*9216 (64 x 144B); B[buf]: 18432 + buf*18432 (128 x 144B);
//   rowsum: 55296 (64 floats)
// ===========================================================================
#define ATT_SMEM 55552

__global__ void __launch_bounds__(256)
attn_mma_kernel(const __half* __restrict__ WhT,
                const float* __restrict__ f1v, const float* __restrict__ fmaxp,
                const float* __restrict__ colB, const float* __restrict__ colD,
                const unsigned* __restrict__ mask,
                float* __restrict__ out, int out_stride,
                __nv_bfloat16* __restrict__ xhi, __nv_bfloat16* __restrict__ xlo) {
    extern __shared__ __align__(16) char smem[];
    uint32_t sb = smem_u32(smem);
    const uint32_t sP = sb;
    const uint32_t sB = sb + 18432;
    float* rsum = (float*)(smem + 55296);

    int h = blockIdx.y;
    int row0 = blockIdx.x * 64;
    int hbase = h * NN;
    int t = threadIdx.x, wid = t >> 5, lane = t & 31;
    int wr = wid & 3, wc = wid >> 2;

    const __half* Whh = WhT + (size_t)(h * 128) * NN;

    // per-head f2 max from 64 partials (all warps redundantly)
    float mF2 = fmaxf(fmaxp[h * 64 + lane], fmaxp[h * 64 + 32 + lane]);
#pragma unroll
    for (int o = 16; o; o >>= 1) mF2 = fmaxf(mF2, __shfl_xor_sync(0xffffffffu, mF2, o));

    // P-gen role: thread covers row pr (0..63), two k-octets kq0, kq0+1
    int pr = t >> 2, kq0 = (t & 3) * 2;
    float f1r = f1v[hbase + row0 + pr];
    float xm = f1r + mF2;
    float m = xm > 0.f ? xm : 0.2f * xm;
    float Ar = __expf(f1r - m);
    float Cr = __expf(0.2f * f1r - m);
    float psum = 0.f;

    const unsigned* mrow = mask + (size_t)(row0 + pr) * 128;
    const float* cBp = colB + hbase;
    const float* cDp = colD + hbase;

    uint32_t a_off = (uint32_t)(wr * 16 + ((lane >> 3) & 1) * 8 + (lane & 7)) * (PSTR2 * 2)
                   + (uint32_t)((lane >> 4) * 8) * 2;
    uint32_t b_roff = (uint32_t)(wc * 64 + (lane >> 4) * 8 + (lane & 7)) * (PSTR2 * 2);
    uint32_t b_koff = (uint32_t)(((lane >> 3) & 1) * 8) * 2;

    float d[8][4] = {};

    auto stage = [&](int c, int buf) {
#pragma unroll
        for (int l = 0; l < 4; l++) {
            int idx = t + l * 256;
            int n = idx >> 3, q = idx & 7;
            size_t go = (size_t)n * NN + c * 64 + q * 8;
            cp16(sB + (uint32_t)buf * 18432 + n * 144 + q * 16, Whh + go);
        }
        CP_COMMIT();
    };
    auto pgen = [&](int c, int buf) {
        unsigned wrd = mrow[2 * c + (kq0 >> 2)];
#pragma unroll
        for (int j2 = 0; j2 < 2; j2++) {
            int o = kq0 + j2;
            int kb = c * 64 + o * 8;
            unsigned w8 = wrd >> ((o & 3) * 8);
            float4 b0 = *(const float4*)(cBp + kb);
            float4 b1 = *(const float4*)(cBp + kb + 4);
            float4 d0 = *(const float4*)(cDp + kb);
            float4 d1 = *(const float4*)(cDp + kb + 4);
            float p[8];
            p[0] = (w8 & 1u)   ? fmaxf(Ar * b0.x, Cr * d0.x) : 0.f;
            p[1] = (w8 & 2u)   ? fmaxf(Ar * b0.y, Cr * d0.y) : 0.f;
            p[2] = (w8 & 4u)   ? fmaxf(Ar * b0.z, Cr * d0.z) : 0.f;
            p[3] = (w8 & 8u)   ? fmaxf(Ar * b0.w, Cr * d0.w) : 0.f;
            p[4] = (w8 & 16u)  ? fmaxf(Ar * b1.x, Cr * d1.x) : 0.f;
            p[5] = (w8 & 32u)  ? fmaxf(Ar * b1.y, Cr * d1.y) : 0.f;
            p[6] = (w8 & 64u)  ? fmaxf(Ar * b1.z, Cr * d1.z) : 0.f;
            p[7] = (w8 & 128u) ? fmaxf(Ar * b1.w, Cr * d1.w) : 0.f;
            psum += ((p[0] + p[1]) + (p[2] + p[3])) + ((p[4] + p[5]) + (p[6] + p[7]));
            uint4 u;
            unsigned* ph = &u.x;
#pragma unroll
            for (int j = 0; j < 4; j++) {
                __half2 h2 = __floats2half2_rn(p[2 * j], p[2 * j + 1]);
                ph[j] = *(unsigned*)&h2;
            }
            *(uint4*)(smem + buf * 9216 + pr * 144 + o * 16) = u;
        }
    };

    stage(0, 0);
    pgen(0, 0);

    for (int c = 0; c < 64; c++) {
        int buf = c & 1;
        CP_WAIT0();
        __syncthreads();     // publish B(c), P(c); readers of buf^1 done
        if (c + 1 < 64) stage(c + 1, buf ^ 1);   // cp.async overlaps mma below
        uint32_t pH = sP + (uint32_t)buf * 9216;
        uint32_t bH = sB + (uint32_t)buf * 18432;
#pragma unroll
        for (int s = 0; s < 4; s++) {
            unsigned ah[4];
            ldsm_x4(ah, pH + a_off + s * 32);
#pragma unroll
            for (int pp = 0; pp < 4; pp++) {
                unsigned bh[4];
                uint32_t boff = b_roff + (uint32_t)(pp * 16) * (PSTR2 * 2) + b_koff + s * 32;
                ldsm_x4(bh, bH + boff);
                mma_f16(d[2 * pp],     ah, bh);
                mma_f16(d[2 * pp + 1], ah, bh + 2);
            }
        }
        if (c + 1 < 64) pgen(c + 1, buf ^ 1);    // fills tensor-pipe drain window
    }

    psum += __shfl_xor_sync(0xffffffffu, psum, 1);
    psum += __shfl_xor_sync(0xffffffffu, psum, 2);
    if ((t & 3) == 0) rsum[pr] = psum;
    __syncthreads();

    int rloc = wr * 16 + (lane >> 2);
    float inv0 = 1.f / rsum[rloc];
    float inv1 = 1.f / rsum[rloc + 8];
    int r0 = row0 + rloc;
    int cbase = h * 128 + wc * 64 + (lane & 3) * 2;
#pragma unroll
    for (int nt = 0; nt < 8; nt++) {
        int col = cbase + nt * 8;
        float v0 = d[nt][0] * inv0, v1 = d[nt][1] * inv0;
        float v2 = d[nt][2] * inv1, v3 = d[nt][3] * inv1;
        v0 = v0 > 0.f ? v0 : expm1f(v0);
        v1 = v1 > 0.f ? v1 : expm1f(v1);
        v2 = v2 > 0.f ? v2 : expm1f(v2);
        v3 = v3 > 0.f ? v3 : expm1f(v3);
        if (xhi) {
            __nv_bfloat16 h0 = __float2bfloat16(v0), h1 = __float2bfloat16(v1);
            __nv_bfloat16 h2 = __float2bfloat16(v2), h3 = __float2bfloat16(v3);
            __nv_bfloat16 l0 = __float2bfloat16(v0 - __bfloat162float(h0));
            __nv_bfloat16 l1 = __float2bfloat16(v1 - __bfloat162float(h1));
            __nv_bfloat16 l2 = __float2bfloat16(v2 - __bfloat162float(h2));
            __nv_bfloat16 l3 = __float2bfloat16(v3 - __bfloat162float(h3));
            *(__nv_bfloat162*)&xhi[(size_t)r0 * 512 + col] = __nv_bfloat162(h0, h1);
            *(__nv_bfloat162*)&xlo[(size_t)r0 * 512 + col] = __nv_bfloat162(l0, l1);
            *(__nv_bfloat162*)&xhi[(size_t)(r0 + 8) * 512 + col] = __nv_bfloat162(h2, h3);
            *(__nv_bfloat162*)&xlo[(size_t)(r0 + 8) * 512 + col] = __nv_bfloat162(l2, l3);
        } else {
            *(float2*)&out[(size_t)r0 * out_stride + col] = make_float2(v0, v1);
            *(float2*)&out[(size_t)(r0 + 8) * out_stride + col] = make_float2(v2, v3);
        }
    }
}

// ===========================================================================
extern "C" void kernel_launch(void* const* d_in, const int* in_sizes, int n_in,
                              void* d_out, int out_size) {
    const int* head = (const int*)d_in[0];
    const int* rel = (const int*)d_in[1];
    const float* adj = (const float*)d_in[2];
    const float* ee = (const float*)d_in[3];
    const float* re = (const float*)d_in[4];
    const float* W0 = (const float*)d_in[5];
    const float* a0 = (const float*)d_in[6];
    const float* Wm = (const float*)d_in[7];
    const float* am = (const float*)d_in[8];
    const float* Wo = (const float*)d_in[9];
    const float* ao = (const float*)d_in[10];
    float* out = (float*)d_out;

    float *f1, *fmaxp, *cB, *cD;
    __half* WhT;
    __nv_bfloat16 *Xhi, *Xlo, *Wth, *Wtl;
    unsigned* mask;
    cudaGetSymbolAddress((void**)&f1, g_f1);
    cudaGetSymbolAddress((void**)&fmaxp, g_fmaxp);
    cudaGetSymbolAddress((void**)&cB, g_colB);
    cudaGetSymbolAddress((void**)&cD, g_colD);
    cudaGetSymbolAddress((void**)&WhT, g_WhT);
    cudaGetSymbolAddress((void**)&Xhi, g_Xhi);
    cudaGetSymbolAddress((void**)&Xlo, g_Xlo);
    cudaGetSymbolAddress((void**)&Wth, g_Wt_hi);
    cudaGetSymbolAddress((void**)&Wtl, g_Wt_lo);
    cudaGetSymbolAddress((void**)&mask, g_mask);

    cudaFuncSetAttribute(attn_mma_kernel, cudaFuncAttributeMaxDynamicSharedMemorySize, ATT_SMEM);
    cudaFuncSetAttribute(gemm_fused_kernel, cudaFuncAttributeMaxDynamicSharedMemorySize, GEMM_SMEM);

    build_mask_kernel<<<NN, 256>>>(adj, mask);
    hrc_kernel<<<NN, 128>>>(head, rel, ee, re, out + (size_t)NN * 128);
    split_kernel<<<(NN * 128 + 255) / 256, 256>>>(ee, Xhi, Xlo, NN * 128);
    wsplit_all_kernel<<<2432, 256>>>(W0, Wm, Wo, Wth, Wtl);

    // ---- layer 0: Fin = 128 ----
    gemm_fused_kernel<<<dim3(64, HH), 256, GEMM_SMEM>>>(Xhi, Xlo, Wth + WT_OFF0, Wtl + WT_OFF0,
                                                        a0, WhT, f1, cB, cD, fmaxp, 128);
    attn_mma_kernel<<<dim3(64, HH), 256, ATT_SMEM>>>(WhT, f1, fmaxp, cB, cD, mask,
                                                     nullptr, 0, Xhi, Xlo);

    // ---- 9 middle layers: Fin = 512 ----
    for (int l = 0; l < NMID; l++) {
        gemm_fused_kernel<<<dim3(64, HH), 256, GEMM_SMEM>>>(Xhi, Xlo,
                                                            Wth + WT_OFFM(l), Wtl + WT_OFFM(l),
                                                            am + (size_t)l * HH * 256,
                                                            WhT, f1, cB, cD, fmaxp, 512);
        attn_mma_kernel<<<dim3(64, HH), 256, ATT_SMEM>>>(WhT, f1, fmaxp, cB, cD, mask,
                                                         nullptr, 0, Xhi, Xlo);
    }

    // ---- output layer: 1 head, Fin = 512 ----
    gemm_fused_kernel<<<dim3(64, 1), 256, GEMM_SMEM>>>(Xhi, Xlo, Wth + WT_OFFO, Wtl + WT_OFFO,
                                                       ao, WhT, f1, cB, cD, fmaxp, 512);
    attn_mma_kernel<<<dim3(64, 1), 256, ATT_SMEM>>>(WhT, f1, fmaxp, cB, cD, mask,
                                                    out, 128, nullptr, nullptr);
}